// round 8
// baseline (speedup 1.0000x reference)
#include <cuda_runtime.h>
#include <math.h>

#define NN 231
#define BT 8
#define THREADS 512
#define NWARP 16
#define MAXM 4096

#define S1S 68    // t1 row stride: 64 data + 4
#define S2S 36    // t2 row stride: 32 + 4
#define T3S 20    // t3 row stride: 16 + 4
#define XFS 476   // FC input stride per graph (464 used + pad)
#define H1S 124   // FC1 out stride
#define H2S 92    // FC2 out stride

typedef unsigned long long ull;

// ---------------- persistent CSR + transposed FC weights -------------
__device__ int    g_row_ptr[NN + 1];
__device__ float2 g_csr_e[MAXM];             // (w, src-as-float-bits)
__device__ float  g_Wt1[120 * 464];          // Wf1^T, k padded to 464
__device__ float  g_Wt2[84 * 120];           // Wf2^T

// =====================================================================
// Prep: deterministic CSR (stable counting sort by dst), rows padded to
// multiple of 4; plus FC weight transposes.
// =====================================================================
__global__ void prep_kernel(const void* __restrict__ ei, int E,
                            const float* __restrict__ Wf1,
                            const float* __restrict__ Wf2) {
    __shared__ short s_src[2304];
    __shared__ short s_dst[2304];
    __shared__ int   deg[NN];
    __shared__ int   pdeg[NN];
    __shared__ int   rp[NN + 1];
    __shared__ float inv[NN];
    __shared__ int   cnt[32][NN];
    __shared__ int   is64;

    const int tid = threadIdx.x;
    const int M = E + NN;

    if (tid == 0) {
        const long long* p = (const long long*)ei;
        int ok = 1;
        for (int i = 0; i < 8; i++) {
            long long v = p[i];
            if (v < 0 || v >= NN) ok = 0;
        }
        is64 = ok;
    }
    for (int n = tid; n < NN; n += blockDim.x) deg[n] = 0;
    __syncthreads();

    for (int e = tid; e < M; e += blockDim.x) {
        int s, d;
        if (e < E) {
            if (is64) {
                s = (int)((const long long*)ei)[e];
                d = (int)((const long long*)ei)[E + e];
            } else {
                s = ((const int*)ei)[e];
                d = ((const int*)ei)[E + e];
            }
        } else {
            s = d = e - E;   // self loops appended after real edges
        }
        s_src[e] = (short)s;
        s_dst[e] = (short)d;
        atomicAdd(&deg[d], 1);
    }
    __syncthreads();

    for (int n = tid; n < NN; n += blockDim.x) {
        inv[n]  = rsqrtf((float)max(deg[n], 1));
        pdeg[n] = (deg[n] + 3) & ~3;
    }
    __syncthreads();
    if (tid == 0) {
        int acc = 0;
        for (int n = 0; n < NN; n++) { rp[n] = acc; acc += pdeg[n]; }
        rp[NN] = acc;
    }
    for (int i = tid; i < 32 * NN; i += blockDim.x)
        ((int*)cnt)[i] = 0;
    __syncthreads();

    const int chunk = (M + 31) / 32;
    if (tid < 32) {
        int e0 = tid * chunk, e1 = min(e0 + chunk, M);
        for (int e = e0; e < e1; e++) cnt[tid][s_dst[e]]++;
    }
    __syncthreads();

    for (int n = tid; n < NN; n += blockDim.x) {
        int run = rp[n];
        for (int t = 0; t < 32; t++) {
            int c = cnt[t][n];
            cnt[t][n] = run;
            run += c;
        }
    }
    __syncthreads();

    if (tid < 32) {
        int e0 = tid * chunk, e1 = min(e0 + chunk, M);
        for (int e = e0; e < e1; e++) {
            int d = s_dst[e], s = s_src[e];
            int pos = cnt[tid][d]++;
            g_csr_e[pos] = make_float2(inv[s] * inv[d], __int_as_float(s));
        }
    }
    __syncthreads();

    for (int n = tid; n < NN; n += blockDim.x) {
        for (int p = deg[n]; p < pdeg[n]; p++)
            g_csr_e[rp[n] + p] = make_float2(0.0f, __int_as_float(0));
    }
    for (int n = tid; n <= NN; n += blockDim.x) g_row_ptr[n] = rp[n];

    // --- transpose FC weights ---
    for (int i = tid; i < 120 * 462; i += blockDim.x) {
        int k = i / 120, j = i - k * 120;
        g_Wt1[j * 464 + k] = Wf1[i];
    }
    for (int j = tid; j < 120; j += blockDim.x) {
        g_Wt1[j * 464 + 462] = 0.0f;
        g_Wt1[j * 464 + 463] = 0.0f;
    }
    for (int i = tid; i < 84 * 120; i += blockDim.x) {
        int k = i / 84, j = i - k * 84;
        g_Wt2[j * 120 + k] = Wf2[i];
    }
}

// =====================================================================
__device__ __forceinline__ float htanh(float x) {
    float y;
    asm("tanh.approx.f32 %0, %1;" : "=f"(y) : "f"(x));
    return y;
}
__device__ __forceinline__ float elu1(float v) {
    return v > 0.0f ? v : (__expf(v) - 1.0f);
}
__device__ __forceinline__ ull ffma2(ull a, ull b, ull c) {
    ull d;
    asm("fma.rn.f32x2 %0, %1, %2, %3;" : "=l"(d) : "l"(a), "l"(b), "l"(c));
    return d;
}
__device__ __forceinline__ ull bcast2(float x) {
    ull d;
    asm("mov.b64 %0, {%1, %1};" : "=l"(d) : "r"(__float_as_uint(x)));
    return d;
}
__device__ __forceinline__ float2 unpack2(ull d) {
    unsigned int lo, hi;
    asm("mov.b64 {%0, %1}, %2;" : "=r"(lo), "=r"(hi) : "l"(d));
    return make_float2(__int_as_float(lo), __int_as_float(hi));
}

// small-weight shared offsets (floats)
#define O_W1  0      // 12x8
#define O_B1  96     // 8
#define O_W2  104    // 8x4
#define O_B2  136    // 4
#define O_W3  140    // 4x2
#define O_B3  148    // 2
#define O_BF1 152    // 120
#define O_BF2 272    // 84
#define O_BF3 356    // 10
#define SMALLSZ 384

#define SM_FLOATS (NN*S1S + NN*S2S + SMALLSZ)
#define SM_BYTES  (SM_FLOATS*4 + (NN+1)*4)

__global__ void __launch_bounds__(THREADS, 2)
gcn_fused_kernel(const float* __restrict__ x,
                 const float* __restrict__ W1, const float* __restrict__ b1,
                 const float* __restrict__ W2, const float* __restrict__ b2,
                 const float* __restrict__ W3, const float* __restrict__ b3,
                 const float* __restrict__ bf1,
                 const float* __restrict__ bf2,
                 const float* __restrict__ Wf3, const float* __restrict__ bf3,
                 float* __restrict__ out, int B) {
    extern __shared__ float sm[];
    float*  S1      = sm;                  // t1 [n][b8][f8], stride 68
    float*  S2      = S1 + NN * S1S;       // t2 [n][b8][f4], stride 36
    float*  s_small = S2 + NN * S2S;
    int*    s_rp    = (int*)(s_small + SMALLSZ);

    const int tid  = threadIdx.x;
    const int wid  = tid >> 5;
    const int lane = tid & 31;
    const int b0   = blockIdx.x * BT;

    // ---- stage rp + small weights ----
    for (int i = tid; i <= NN; i += THREADS) s_rp[i] = g_row_ptr[i];
    for (int i = tid; i < 96;  i += THREADS) s_small[O_W1 + i] = W1[i];
    for (int i = tid; i < 8;   i += THREADS) s_small[O_B1 + i] = b1[i];
    for (int i = tid; i < 32;  i += THREADS) s_small[O_W2 + i] = W2[i];
    for (int i = tid; i < 4;   i += THREADS) s_small[O_B2 + i] = b2[i];
    for (int i = tid; i < 8;   i += THREADS) s_small[O_W3 + i] = W3[i];
    for (int i = tid; i < 2;   i += THREADS) s_small[O_B3 + i] = b3[i];
    for (int i = tid; i < 120; i += THREADS) s_small[O_BF1 + i] = bf1[i];
    for (int i = tid; i < 84;  i += THREADS) s_small[O_BF2 + i] = bf2[i];
    for (int i = tid; i < 10;  i += THREADS) s_small[O_BF3 + i] = bf3[i];
    __syncthreads();

    // ========== T1: t1 = x @ W1 -> S1[n][b][f] (packed) ==========
    for (int idx = tid; idx < NN * BT; idx += THREADS) {
        const int b = idx / NN, n = idx - b * NN;
        const int g = b0 + b;
        float xa[12];
        if (g < B) {
            const float4* xp = (const float4*)(x + ((size_t)g * NN + n) * 12);
            float4 v0 = xp[0], v1 = xp[1], v2 = xp[2];
            xa[0] = v0.x; xa[1] = v0.y; xa[2]  = v0.z; xa[3]  = v0.w;
            xa[4] = v1.x; xa[5] = v1.y; xa[6]  = v1.z; xa[7]  = v1.w;
            xa[8] = v2.x; xa[9] = v2.y; xa[10] = v2.z; xa[11] = v2.w;
        } else {
            #pragma unroll
            for (int c = 0; c < 12; c++) xa[c] = 0.0f;
        }
        ull a0 = 0, a1 = 0, a2 = 0, a3 = 0;
        #pragma unroll
        for (int c = 0; c < 12; c++) {
            const ull xb = bcast2(xa[c]);
            const ull* wrow = (const ull*)(s_small + O_W1 + c * 8);
            a0 = ffma2(xb, wrow[0], a0);
            a1 = ffma2(xb, wrow[1], a1);
            a2 = ffma2(xb, wrow[2], a2);
            a3 = ffma2(xb, wrow[3], a3);
        }
        float* dst = S1 + n * S1S + b * 8;
        *(ulonglong2*)dst       = make_ulonglong2(a0, a1);
        *(ulonglong2*)(dst + 4) = make_ulonglong2(a2, a3);
    }
    __syncthreads();

    // ========== A1: h1 = tanh(agg(t1)+b1); t2 = h1@W2 -> S2 ==========
    // half-warp per edge; lh owns float4: b = lh>>1, fq = (lh&1)*4
    {
        const int h  = lane >> 4;
        const int lh = lane & 15;
        const int fq = (lh & 1) * 4;
        float w2r[4][4];
        #pragma unroll
        for (int i = 0; i < 4; i++)
            #pragma unroll
            for (int f2 = 0; f2 < 4; f2++)
                w2r[i][f2] = s_small[O_W2 + (fq + i) * 4 + f2];
        const float4 b1v = *(const float4*)(s_small + O_B1 + fq);

        for (int n = wid; n < NN; n += NWARP) {
            const int j0 = s_rp[n], j1 = s_rp[n + 1];
            ull a01 = 0, a23 = 0;
            for (int j = j0; j < j1; j += 2) {
                const float2 e = __ldg(&g_csr_e[j + h]);
                const ull ww = bcast2(e.x);
                const ulonglong2 v =
                    *(const ulonglong2*)(S1 + __float_as_int(e.y) * S1S + lh * 4);
                a01 = ffma2(v.x, ww, a01);
                a23 = ffma2(v.y, ww, a23);
            }
            float2 u0 = unpack2(a01), u1 = unpack2(a23);
            float ax = u0.x, ay = u0.y, az = u1.x, aw = u1.y;
            ax += __shfl_xor_sync(~0u, ax, 16);
            ay += __shfl_xor_sync(~0u, ay, 16);
            az += __shfl_xor_sync(~0u, az, 16);
            aw += __shfl_xor_sync(~0u, aw, 16);
            const float tx = htanh(ax + b1v.x);
            const float ty = htanh(ay + b1v.y);
            const float tz = htanh(az + b1v.z);
            const float tw = htanh(aw + b1v.w);
            float4 p;
            p.x = tx * w2r[0][0] + ty * w2r[1][0] + tz * w2r[2][0] + tw * w2r[3][0];
            p.y = tx * w2r[0][1] + ty * w2r[1][1] + tz * w2r[2][1] + tw * w2r[3][1];
            p.z = tx * w2r[0][2] + ty * w2r[1][2] + tz * w2r[2][2] + tw * w2r[3][2];
            p.w = tx * w2r[0][3] + ty * w2r[1][3] + tz * w2r[2][3] + tw * w2r[3][3];
            p.x += __shfl_xor_sync(~0u, p.x, 1);
            p.y += __shfl_xor_sync(~0u, p.y, 1);
            p.z += __shfl_xor_sync(~0u, p.z, 1);
            p.w += __shfl_xor_sync(~0u, p.w, 1);
            if (lane < 16 && !(lane & 1))
                *(float4*)(S2 + n * S2S + (lh >> 1) * 4) = p;
        }
    }
    __syncthreads();

    // ========== A2: h2 = tanh(agg(t2)+b2); t3 = h2@W3 -> S1 (t3) =====
    {
        const int q  = lane >> 3;
        const int lb = lane & 7;
        const float4 b2v = *(const float4*)(s_small + O_B2);
        float w30[4], w31[4];
        #pragma unroll
        for (int f = 0; f < 4; f++) {
            w30[f] = s_small[O_W3 + f * 2 + 0];
            w31[f] = s_small[O_W3 + f * 2 + 1];
        }
        for (int n = wid; n < NN; n += NWARP) {
            const int j0 = s_rp[n], j1 = s_rp[n + 1];
            ull a01 = 0, a23 = 0;
            for (int j = j0; j < j1; j += 4) {
                const float2 e = __ldg(&g_csr_e[j + q]);
                const ull ww = bcast2(e.x);
                const ulonglong2 v =
                    *(const ulonglong2*)(S2 + __float_as_int(e.y) * S2S + lb * 4);
                a01 = ffma2(v.x, ww, a01);
                a23 = ffma2(v.y, ww, a23);
            }
            float2 u0 = unpack2(a01), u1 = unpack2(a23);
            float ax = u0.x, ay = u0.y, az = u1.x, aw = u1.y;
            #pragma unroll
            for (int off = 8; off <= 16; off <<= 1) {
                ax += __shfl_xor_sync(~0u, ax, off);
                ay += __shfl_xor_sync(~0u, ay, off);
                az += __shfl_xor_sync(~0u, az, off);
                aw += __shfl_xor_sync(~0u, aw, off);
            }
            const float t0 = htanh(ax + b2v.x);
            const float t1 = htanh(ay + b2v.y);
            const float t2 = htanh(az + b2v.z);
            const float t3 = htanh(aw + b2v.w);
            const float p0 = t0 * w30[0] + t1 * w30[1] + t2 * w30[2] + t3 * w30[3];
            const float p1 = t0 * w31[0] + t1 * w31[1] + t2 * w31[2] + t3 * w31[3];
            if (lane < 8)
                *(float2*)(S1 + n * T3S + lb * 2) = make_float2(p0, p1);
        }
    }
    __syncthreads();

    // ========== A3: h3 = agg(t3)+b3 -> xfc[b][2n+c] in S2 ============
    {
        const int o  = lane >> 3;
        const int lb = lane & 7;
        const float b3x = s_small[O_B3 + 0];
        const float b3y = s_small[O_B3 + 1];
        for (int n = wid; n < NN; n += NWARP) {
            const int j0 = s_rp[n], j1 = s_rp[n + 1];
            float ax = 0.0f, ay = 0.0f;
            for (int j = j0; j < j1; j += 4) {
                const float2 e = __ldg(&g_csr_e[j + o]);
                const float2 v = *(const float2*)(S1 + __float_as_int(e.y) * T3S + lb * 2);
                ax += e.x * v.x;
                ay += e.x * v.y;
            }
            #pragma unroll
            for (int off = 8; off <= 16; off <<= 1) {
                ax += __shfl_xor_sync(~0u, ax, off);
                ay += __shfl_xor_sync(~0u, ay, off);
            }
            if (lane < 8)
                *(float2*)(S2 + lb * XFS + 2 * n) = make_float2(ax + b3x, ay + b3y);
        }
        // zero xfc pad k = 462, 463 (read by the padded FC1 loop)
        if (tid < 16)
            S2[(tid >> 1) * XFS + 462 + (tid & 1)] = 0.0f;
    }
    __syncthreads();

    // ========== FC1: xfc[8,464] @ Wt1[120][464] + bf1 -> elu -> S1 ===
    // 480 threads: j (0..119) x bq (2: 4 b's) x kh (2: k halves)
    {
        const bool active = tid < 480;
        const int j  = tid % 120;
        const int bq = (tid / 120) & 1;
        const int kh = tid / 240;      // 0/1 for active threads
        float r0 = 0.f, r1 = 0.f, r2 = 0.f, r3 = 0.f;

        if (active) {
            ull c0 = 0, c1 = 0, c2 = 0, c3 = 0;
            const float* wrow = g_Wt1 + j * 464;
            const float* xb   = S2 + (bq * 4) * XFS;
            const int k0 = kh * 232;
            #pragma unroll 2
            for (int k = k0; k < k0 + 232; k += 4) {
                const ulonglong2 w  = __ldg((const ulonglong2*)(wrow + k));
                const ulonglong2 v0 = *(const ulonglong2*)(xb + k);
                const ulonglong2 v1 = *(const ulonglong2*)(xb + XFS + k);
                const ulonglong2 v2 = *(const ulonglong2*)(xb + 2 * XFS + k);
                const ulonglong2 v3 = *(const ulonglong2*)(xb + 3 * XFS + k);
                c0 = ffma2(v0.x, w.x, c0); c0 = ffma2(v0.y, w.y, c0);
                c1 = ffma2(v1.x, w.x, c1); c1 = ffma2(v1.y, w.y, c1);
                c2 = ffma2(v2.x, w.x, c2); c2 = ffma2(v2.y, w.y, c2);
                c3 = ffma2(v3.x, w.x, c3); c3 = ffma2(v3.y, w.y, c3);
            }
            float2 u;
            u = unpack2(c0); r0 = u.x + u.y;
            u = unpack2(c1); r1 = u.x + u.y;
            u = unpack2(c2); r2 = u.x + u.y;
            u = unpack2(c3); r3 = u.x + u.y;
            if (kh)
                *(float4*)(S1 + 4096 + (j * 2 + bq) * 4) =
                    make_float4(r0, r1, r2, r3);
        }
        __syncthreads();
        if (active && kh == 0) {
            const float4 o = *(const float4*)(S1 + 4096 + (j * 2 + bq) * 4);
            const float bf = s_small[O_BF1 + j];
            const int bb = bq * 4;
            S1[(bb + 0) * H1S + j] = elu1(r0 + o.x + bf);
            S1[(bb + 1) * H1S + j] = elu1(r1 + o.y + bf);
            S1[(bb + 2) * H1S + j] = elu1(r2 + o.z + bf);
            S1[(bb + 3) * H1S + j] = elu1(r3 + o.w + bf);
        }
    }
    __syncthreads();

    // ========== FC2: h1[8,120] @ Wt2[84][120] + bf2 -> elu -> S2 =====
    if (tid < 336) {
        const int j  = tid % 84;
        const int bh = tid / 84;       // 0..3, 2 b each
        ull a0 = 0, a1 = 0;
        const float* wrow = g_Wt2 + j * 120;
        const float* x0 = S1 + (bh * 2) * H1S;
        const float* x1 = x0 + H1S;
        #pragma unroll 3
        for (int k = 0; k < 120; k += 4) {
            const ulonglong2 w  = __ldg((const ulonglong2*)(wrow + k));
            const ulonglong2 v0 = *(const ulonglong2*)(x0 + k);
            const ulonglong2 v1 = *(const ulonglong2*)(x1 + k);
            a0 = ffma2(v0.x, w.x, a0); a0 = ffma2(v0.y, w.y, a0);
            a1 = ffma2(v1.x, w.x, a1); a1 = ffma2(v1.y, w.y, a1);
        }
        const float2 u0 = unpack2(a0), u1 = unpack2(a1);
        const float bf = s_small[O_BF2 + j];
        S2[(bh * 2 + 0) * H2S + j] = elu1(u0.x + u0.y + bf);
        S2[(bh * 2 + 1) * H2S + j] = elu1(u1.x + u1.y + bf);
    }
    __syncthreads();

    // ========== FC3: h2[8,84] @ Wf3[84,10] + bf3 -> out ==============
    if (tid < 80) {
        const int b = tid & 7, j = tid >> 3;    // j 0..9
        float acc = s_small[O_BF3 + j];
        const float* xin = S2 + b * H2S;
        #pragma unroll 3
        for (int k = 0; k < 84; k += 4) {
            const float4 v = *(const float4*)(xin + k);
            acc += v.x * __ldg(Wf3 + (k + 0) * 10 + j);
            acc += v.y * __ldg(Wf3 + (k + 1) * 10 + j);
            acc += v.z * __ldg(Wf3 + (k + 2) * 10 + j);
            acc += v.w * __ldg(Wf3 + (k + 3) * 10 + j);
        }
        const int g = b0 + b;
        if (g < B) out[(size_t)g * 10 + j] = acc;
    }
}

// =====================================================================
extern "C" void kernel_launch(void* const* d_in, const int* in_sizes, int n_in,
                              void* d_out, int out_size) {
    const float* x   = (const float*)d_in[0];
    const void*  ei  = d_in[1];
    const float* W1  = (const float*)d_in[2];
    const float* b1  = (const float*)d_in[3];
    const float* W2  = (const float*)d_in[4];
    const float* b2  = (const float*)d_in[5];
    const float* W3  = (const float*)d_in[6];
    const float* b3  = (const float*)d_in[7];
    const float* Wf1 = (const float*)d_in[8];
    const float* bf1 = (const float*)d_in[9];
    const float* Wf2 = (const float*)d_in[10];
    const float* bf2 = (const float*)d_in[11];
    const float* Wf3 = (const float*)d_in[12];
    const float* bf3 = (const float*)d_in[13];
    float* out = (float*)d_out;

    const int B = in_sizes[0] / (NN * 12);
    const int E = in_sizes[1] / 2;

    prep_kernel<<<1, 256>>>(ei, E, Wf1, Wf2);

    static int smem_set = 0;
    if (!smem_set) {
        cudaFuncSetAttribute(gcn_fused_kernel,
                             cudaFuncAttributeMaxDynamicSharedMemorySize,
                             SM_BYTES);
        smem_set = 1;
    }

    const int blocks = (B + BT - 1) / BT;
    gcn_fused_kernel<<<blocks, THREADS, SM_BYTES>>>(
        x, W1, b1, W2, b2, W3, b3, bf1, bf2, Wf3, bf3,
        out, B);
}

// round 9
// speedup vs baseline: 1.2790x; 1.2790x over previous
#include <cuda_runtime.h>
#include <math.h>

#define NN 231
#define BT 8
#define THREADS 512
#define NWARP 16
#define MAXM 4096

#define S1S 68    // t1 row stride: 64 data + 4
#define S2S 36    // t2 row stride: 32 + 4
#define T3S 20    // t3 row stride: 16 + 4
#define XFS 476   // FC input stride per graph (464 used + pad)
#define H1S 124   // FC1 out stride
#define H2S 92    // FC2 out stride

typedef unsigned long long ull;

// ---------------- persistent CSR built by prep kernel ----------------
// three copies with pre-scaled source offsets (saves an IMAD per edge)
__device__ int    g_row_ptr[NN + 1];
__device__ float2 g_e1[MAXM];   // (w, src*S1S as int bits)
__device__ float2 g_e2[MAXM];   // (w, src*S2S)
__device__ float2 g_e3[MAXM];   // (w, src*T3S)

// =====================================================================
// Prep: deterministic CSR (stable counting sort by dst), rows padded to
// multiple of 4 with (w=0, off=0) dummies.
// =====================================================================
__global__ void prep_kernel(const void* __restrict__ ei, int E) {
    __shared__ short s_src[2304];
    __shared__ short s_dst[2304];
    __shared__ int   deg[NN];
    __shared__ int   pdeg[NN];
    __shared__ int   rp[NN + 1];
    __shared__ float inv[NN];
    __shared__ int   cnt[32][NN];
    __shared__ int   is64;

    const int tid = threadIdx.x;
    const int M = E + NN;

    if (tid == 0) {
        const long long* p = (const long long*)ei;
        int ok = 1;
        for (int i = 0; i < 8; i++) {
            long long v = p[i];
            if (v < 0 || v >= NN) ok = 0;
        }
        is64 = ok;
    }
    for (int n = tid; n < NN; n += blockDim.x) deg[n] = 0;
    __syncthreads();

    for (int e = tid; e < M; e += blockDim.x) {
        int s, d;
        if (e < E) {
            if (is64) {
                s = (int)((const long long*)ei)[e];
                d = (int)((const long long*)ei)[E + e];
            } else {
                s = ((const int*)ei)[e];
                d = ((const int*)ei)[E + e];
            }
        } else {
            s = d = e - E;   // self loops appended after real edges
        }
        s_src[e] = (short)s;
        s_dst[e] = (short)d;
        atomicAdd(&deg[d], 1);
    }
    __syncthreads();

    for (int n = tid; n < NN; n += blockDim.x) {
        inv[n]  = rsqrtf((float)max(deg[n], 1));
        pdeg[n] = (deg[n] + 3) & ~3;
    }
    __syncthreads();
    if (tid == 0) {
        int acc = 0;
        for (int n = 0; n < NN; n++) { rp[n] = acc; acc += pdeg[n]; }
        rp[NN] = acc;
    }
    for (int i = tid; i < 32 * NN; i += blockDim.x)
        ((int*)cnt)[i] = 0;
    __syncthreads();

    const int chunk = (M + 31) / 32;
    if (tid < 32) {
        int e0 = tid * chunk, e1 = min(e0 + chunk, M);
        for (int e = e0; e < e1; e++) cnt[tid][s_dst[e]]++;
    }
    __syncthreads();

    for (int n = tid; n < NN; n += blockDim.x) {
        int run = rp[n];
        for (int t = 0; t < 32; t++) {
            int c = cnt[t][n];
            cnt[t][n] = run;
            run += c;
        }
    }
    __syncthreads();

    if (tid < 32) {
        int e0 = tid * chunk, e1 = min(e0 + chunk, M);
        for (int e = e0; e < e1; e++) {
            int d = s_dst[e], s = s_src[e];
            int pos = cnt[tid][d]++;
            float w = inv[s] * inv[d];
            g_e1[pos] = make_float2(w, __int_as_float(s * S1S));
            g_e2[pos] = make_float2(w, __int_as_float(s * S2S));
            g_e3[pos] = make_float2(w, __int_as_float(s * T3S));
        }
    }
    __syncthreads();

    for (int n = tid; n < NN; n += blockDim.x) {
        for (int p = deg[n]; p < pdeg[n]; p++) {
            int pos = rp[n] + p;
            g_e1[pos] = make_float2(0.0f, __int_as_float(0));
            g_e2[pos] = make_float2(0.0f, __int_as_float(0));
            g_e3[pos] = make_float2(0.0f, __int_as_float(0));
        }
    }
    for (int n = tid; n <= NN; n += blockDim.x) g_row_ptr[n] = rp[n];
}

// =====================================================================
__device__ __forceinline__ float htanh(float x) {
    float y;
    asm("tanh.approx.f32 %0, %1;" : "=f"(y) : "f"(x));
    return y;
}
__device__ __forceinline__ float elu1(float v) {
    return v > 0.0f ? v : (__expf(v) - 1.0f);
}
__device__ __forceinline__ ull ffma2(ull a, ull b, ull c) {
    ull d;
    asm("fma.rn.f32x2 %0, %1, %2, %3;" : "=l"(d) : "l"(a), "l"(b), "l"(c));
    return d;
}
__device__ __forceinline__ ull bcast2(float x) {
    ull d;
    asm("mov.b64 %0, {%1, %1};" : "=l"(d) : "r"(__float_as_uint(x)));
    return d;
}
__device__ __forceinline__ float2 unpack2(ull d) {
    unsigned int lo, hi;
    asm("mov.b64 {%0, %1}, %2;" : "=r"(lo), "=r"(hi) : "l"(d));
    return make_float2(__int_as_float(lo), __int_as_float(hi));
}

// small-weight shared offsets (floats)
#define O_W1  0      // 12x8
#define O_B1  96     // 8
#define O_W2  104    // 8x4
#define O_B2  136    // 4
#define O_W3  140    // 4x2
#define O_B3  148    // 2
#define O_BF1 152    // 120
#define O_BF2 272    // 84
#define O_BF3 356    // 10
#define SMALLSZ 384

#define SM_FLOATS (NN*S1S + NN*S2S + SMALLSZ)
#define SM_BYTES  (SM_FLOATS*4 + (NN+1)*4)

__global__ void __launch_bounds__(THREADS, 2)
gcn_fused_kernel(const float* __restrict__ x,
                 const float* __restrict__ W1, const float* __restrict__ b1,
                 const float* __restrict__ W2, const float* __restrict__ b2,
                 const float* __restrict__ W3, const float* __restrict__ b3,
                 const float* __restrict__ Wf1, const float* __restrict__ bf1,
                 const float* __restrict__ Wf2, const float* __restrict__ bf2,
                 const float* __restrict__ Wf3, const float* __restrict__ bf3,
                 float* __restrict__ out, int B) {
    extern __shared__ float sm[];
    float*  S1      = sm;                  // t1 [n][b8][f8], stride 68
    float*  S2      = S1 + NN * S1S;       // t2 [n][b8][f4], stride 36
    float*  s_small = S2 + NN * S2S;
    int*    s_rp    = (int*)(s_small + SMALLSZ);

    const int tid  = threadIdx.x;
    const int wid  = tid >> 5;
    const int lane = tid & 31;
    const int b0   = blockIdx.x * BT;

    // ---- stage rp + small weights ----
    for (int i = tid; i <= NN; i += THREADS) s_rp[i] = g_row_ptr[i];
    for (int i = tid; i < 96;  i += THREADS) s_small[O_W1 + i] = W1[i];
    for (int i = tid; i < 8;   i += THREADS) s_small[O_B1 + i] = b1[i];
    for (int i = tid; i < 32;  i += THREADS) s_small[O_W2 + i] = W2[i];
    for (int i = tid; i < 4;   i += THREADS) s_small[O_B2 + i] = b2[i];
    for (int i = tid; i < 8;   i += THREADS) s_small[O_W3 + i] = W3[i];
    for (int i = tid; i < 2;   i += THREADS) s_small[O_B3 + i] = b3[i];
    for (int i = tid; i < 120; i += THREADS) s_small[O_BF1 + i] = bf1[i];
    for (int i = tid; i < 84;  i += THREADS) s_small[O_BF2 + i] = bf2[i];
    for (int i = tid; i < 10;  i += THREADS) s_small[O_BF3 + i] = bf3[i];
    __syncthreads();

    // ========== T1: t1 = x @ W1 -> S1[n][b][f] ==========
    for (int idx = tid; idx < NN * BT; idx += THREADS) {
        const int b = idx / NN, n = idx - b * NN;
        const int g = b0 + b;
        float xa[12];
        if (g < B) {
            const float4* xp = (const float4*)(x + ((size_t)g * NN + n) * 12);
            float4 v0 = xp[0], v1 = xp[1], v2 = xp[2];
            xa[0] = v0.x; xa[1] = v0.y; xa[2]  = v0.z; xa[3]  = v0.w;
            xa[4] = v1.x; xa[5] = v1.y; xa[6]  = v1.z; xa[7]  = v1.w;
            xa[8] = v2.x; xa[9] = v2.y; xa[10] = v2.z; xa[11] = v2.w;
        } else {
            #pragma unroll
            for (int c = 0; c < 12; c++) xa[c] = 0.0f;
        }
        float t[8];
        #pragma unroll
        for (int f = 0; f < 8; f++) {
            float a = 0.0f;
            #pragma unroll
            for (int c = 0; c < 12; c++) a += xa[c] * s_small[O_W1 + c * 8 + f];
            t[f] = a;
        }
        float* dst = S1 + n * S1S + b * 8;
        *(float4*)dst       = make_float4(t[0], t[1], t[2], t[3]);
        *(float4*)(dst + 4) = make_float4(t[4], t[5], t[6], t[7]);
    }
    __syncthreads();

    // ========== A1: h1 = tanh(agg(t1)+b1); t2 = h1@W2 -> S2 ==========
    // half-warp per edge; lh owns float4: b = lh>>1, fq = (lh&1)*4
    {
        const int h  = lane >> 4;
        const int lh = lane & 15;
        const int fq = (lh & 1) * 4;
        float w2r[4][4];
        #pragma unroll
        for (int i = 0; i < 4; i++)
            #pragma unroll
            for (int f2 = 0; f2 < 4; f2++)
                w2r[i][f2] = s_small[O_W2 + (fq + i) * 4 + f2];
        const float4 b1v = *(const float4*)(s_small + O_B1 + fq);
        const float* S1p = S1 + lh * 4;

        for (int n = wid; n < NN; n += NWARP) {
            const int j0 = s_rp[n], j1 = s_rp[n + 1];
            float4 acc = make_float4(0.f, 0.f, 0.f, 0.f);
            for (int j = j0; j < j1; j += 2) {
                const float2 e = __ldg(&g_e1[j + h]);
                const float4 v = *(const float4*)(S1p + __float_as_int(e.y));
                acc.x += e.x * v.x; acc.y += e.x * v.y;
                acc.z += e.x * v.z; acc.w += e.x * v.w;
            }
            acc.x += __shfl_xor_sync(~0u, acc.x, 16);
            acc.y += __shfl_xor_sync(~0u, acc.y, 16);
            acc.z += __shfl_xor_sync(~0u, acc.z, 16);
            acc.w += __shfl_xor_sync(~0u, acc.w, 16);
            const float tx = htanh(acc.x + b1v.x);
            const float ty = htanh(acc.y + b1v.y);
            const float tz = htanh(acc.z + b1v.z);
            const float tw = htanh(acc.w + b1v.w);
            float4 p;
            p.x = tx * w2r[0][0] + ty * w2r[1][0] + tz * w2r[2][0] + tw * w2r[3][0];
            p.y = tx * w2r[0][1] + ty * w2r[1][1] + tz * w2r[2][1] + tw * w2r[3][1];
            p.z = tx * w2r[0][2] + ty * w2r[1][2] + tz * w2r[2][2] + tw * w2r[3][2];
            p.w = tx * w2r[0][3] + ty * w2r[1][3] + tz * w2r[2][3] + tw * w2r[3][3];
            p.x += __shfl_xor_sync(~0u, p.x, 1);
            p.y += __shfl_xor_sync(~0u, p.y, 1);
            p.z += __shfl_xor_sync(~0u, p.z, 1);
            p.w += __shfl_xor_sync(~0u, p.w, 1);
            if (lane < 16 && !(lane & 1))
                *(float4*)(S2 + n * S2S + (lh >> 1) * 4) = p;
        }
    }
    __syncthreads();

    // ========== A2: h2 = tanh(agg(t2)+b2); t3 = h2@W3 -> S1 (t3) =====
    {
        const int q  = lane >> 3;
        const int lb = lane & 7;
        const float4 b2v = *(const float4*)(s_small + O_B2);
        float w30[4], w31[4];
        #pragma unroll
        for (int f = 0; f < 4; f++) {
            w30[f] = s_small[O_W3 + f * 2 + 0];
            w31[f] = s_small[O_W3 + f * 2 + 1];
        }
        const float* S2p = S2 + lb * 4;
        for (int n = wid; n < NN; n += NWARP) {
            const int j0 = s_rp[n], j1 = s_rp[n + 1];
            float4 acc = make_float4(0.f, 0.f, 0.f, 0.f);
            for (int j = j0; j < j1; j += 4) {
                const float2 e = __ldg(&g_e2[j + q]);
                const float4 v = *(const float4*)(S2p + __float_as_int(e.y));
                acc.x += e.x * v.x; acc.y += e.x * v.y;
                acc.z += e.x * v.z; acc.w += e.x * v.w;
            }
            #pragma unroll
            for (int off = 8; off <= 16; off <<= 1) {
                acc.x += __shfl_xor_sync(~0u, acc.x, off);
                acc.y += __shfl_xor_sync(~0u, acc.y, off);
                acc.z += __shfl_xor_sync(~0u, acc.z, off);
                acc.w += __shfl_xor_sync(~0u, acc.w, off);
            }
            const float t0 = htanh(acc.x + b2v.x);
            const float t1 = htanh(acc.y + b2v.y);
            const float t2 = htanh(acc.z + b2v.z);
            const float t3 = htanh(acc.w + b2v.w);
            const float p0 = t0 * w30[0] + t1 * w30[1] + t2 * w30[2] + t3 * w30[3];
            const float p1 = t0 * w31[0] + t1 * w31[1] + t2 * w31[2] + t3 * w31[3];
            if (lane < 8)
                *(float2*)(S1 + n * T3S + lb * 2) = make_float2(p0, p1);
        }
    }
    __syncthreads();

    // ========== A3: h3 = agg(t3)+b3 -> xfc[b][2n+c] in S2 ============
    {
        const int o  = lane >> 3;
        const int lb = lane & 7;
        const float b3x = s_small[O_B3 + 0];
        const float b3y = s_small[O_B3 + 1];
        const float* T3p = S1 + lb * 2;
        for (int n = wid; n < NN; n += NWARP) {
            const int j0 = s_rp[n], j1 = s_rp[n + 1];
            float ax = 0.0f, ay = 0.0f;
            for (int j = j0; j < j1; j += 4) {
                const float2 e = __ldg(&g_e3[j + o]);
                const float2 v = *(const float2*)(T3p + __float_as_int(e.y));
                ax += e.x * v.x;
                ay += e.x * v.y;
            }
            #pragma unroll
            for (int off = 8; off <= 16; off <<= 1) {
                ax += __shfl_xor_sync(~0u, ax, off);
                ay += __shfl_xor_sync(~0u, ay, off);
            }
            if (lane < 8)
                *(float2*)(S2 + lb * XFS + 2 * n) = make_float2(ax + b3x, ay + b3y);
        }
        // zero xfc pad k = 462, 463 (read by the padded FC1 loop)
        if (tid < 16)
            S2[(tid >> 1) * XFS + 462 + (tid & 1)] = 0.0f;
    }
    __syncthreads();

    // ========== FC1: xfc[8,464] @ Wf1[462,120] + bf1 -> elu -> S1 ====
    // 480 threads: kh (2 k-halves) x jg (30: 4 j each) x b (8)
    {
        const bool active = tid < 480;
        const int kh = tid / 240;
        const int r  = tid - kh * 240;      // 0..239
        const int jg = r >> 3;              // 0..29
        const int b  = r & 7;
        const int j0 = jg * 4;
        ull c01 = 0, c23 = 0;

        if (active) {
            const float* wb  = Wf1 + j0;
            const float* xin = S2 + b * XFS;
            const int k0 = kh * 232;
            #pragma unroll 2
            for (int k = k0; k < k0 + 232; k += 4) {
                const float4 v = *(const float4*)(xin + k);
                // weights for k..k+3 (rows), 4 j packed as 2 ull each row
                const ulonglong2 w0 = __ldg((const ulonglong2*)(wb + (k + 0) * 120));
                const ulonglong2 w1 = __ldg((const ulonglong2*)(wb + (k + 1) * 120));
                const ulonglong2 w2 = __ldg((const ulonglong2*)(wb + (k + 2) * 120));
                const ulonglong2 w3 = __ldg((const ulonglong2*)(wb + (k + 3) * 120));
                const ull vx = bcast2(v.x), vy = bcast2(v.y);
                const ull vz = bcast2(v.z), vw = bcast2(v.w);
                c01 = ffma2(vx, w0.x, c01); c23 = ffma2(vx, w0.y, c23);
                c01 = ffma2(vy, w1.x, c01); c23 = ffma2(vy, w1.y, c23);
                c01 = ffma2(vz, w2.x, c01); c23 = ffma2(vz, w2.y, c23);
                c01 = ffma2(vw, w3.x, c01); c23 = ffma2(vw, w3.y, c23);
            }
            if (kh) {
                const float2 u0 = unpack2(c01), u1 = unpack2(c23);
                *(float4*)(S1 + 4096 + r * 4) =
                    make_float4(u0.x, u0.y, u1.x, u1.y);
            }
        }
        __syncthreads();
        if (active && kh == 0) {
            const float4 o = *(const float4*)(S1 + 4096 + r * 4);
            const float2 u0 = unpack2(c01), u1 = unpack2(c23);
            const float4 bf = *(const float4*)(s_small + O_BF1 + j0);
            float4 res;
            res.x = elu1(u0.x + o.x + bf.x);
            res.y = elu1(u0.y + o.y + bf.y);
            res.z = elu1(u1.x + o.z + bf.z);
            res.w = elu1(u1.y + o.w + bf.w);
            *(float4*)(S1 + b * H1S + j0) = res;
        }
    }
    __syncthreads();

    // ========== FC2: h1[8,120] @ Wf2[120,84] + bf2 -> elu -> S2 ======
    if (tid < 336) {
        const int b = tid & 7, jg = tid >> 3;   // jg 0..41
        const int j0 = jg * 2;
        float2 acc = make_float2(s_small[O_BF2 + j0], s_small[O_BF2 + j0 + 1]);
        const float* xin = S1 + b * H1S;
        const float* wb  = Wf2 + j0;
        #pragma unroll 2
        for (int k = 0; k < 120; k += 4) {
            const float4 v  = *(const float4*)(xin + k);
            const float2 w0 = __ldg((const float2*)(wb + (k + 0) * 84));
            const float2 w1 = __ldg((const float2*)(wb + (k + 1) * 84));
            const float2 w2 = __ldg((const float2*)(wb + (k + 2) * 84));
            const float2 w3 = __ldg((const float2*)(wb + (k + 3) * 84));
            acc.x += v.x * w0.x + v.y * w1.x + v.z * w2.x + v.w * w3.x;
            acc.y += v.x * w0.y + v.y * w1.y + v.z * w2.y + v.w * w3.y;
        }
        S2[b * H2S + j0 + 0] = elu1(acc.x);
        S2[b * H2S + j0 + 1] = elu1(acc.y);
    }
    __syncthreads();

    // ========== FC3: h2[8,84] @ Wf3[84,10] + bf3 -> out ==============
    if (tid < 80) {
        const int b = tid & 7, j = tid >> 3;    // j 0..9
        float acc = s_small[O_BF3 + j];
        const float* xin = S2 + b * H2S;
        #pragma unroll 3
        for (int k = 0; k < 84; k += 4) {
            const float4 v = *(const float4*)(xin + k);
            acc += v.x * __ldg(Wf3 + (k + 0) * 10 + j);
            acc += v.y * __ldg(Wf3 + (k + 1) * 10 + j);
            acc += v.z * __ldg(Wf3 + (k + 2) * 10 + j);
            acc += v.w * __ldg(Wf3 + (k + 3) * 10 + j);
        }
        const int g = b0 + b;
        if (g < B) out[(size_t)g * 10 + j] = acc;
    }
}

// =====================================================================
extern "C" void kernel_launch(void* const* d_in, const int* in_sizes, int n_in,
                              void* d_out, int out_size) {
    const float* x   = (const float*)d_in[0];
    const void*  ei  = d_in[1];
    const float* W1  = (const float*)d_in[2];
    const float* b1  = (const float*)d_in[3];
    const float* W2  = (const float*)d_in[4];
    const float* b2  = (const float*)d_in[5];
    const float* W3  = (const float*)d_in[6];
    const float* b3  = (const float*)d_in[7];
    const float* Wf1 = (const float*)d_in[8];
    const float* bf1 = (const float*)d_in[9];
    const float* Wf2 = (const float*)d_in[10];
    const float* bf2 = (const float*)d_in[11];
    const float* Wf3 = (const float*)d_in[12];
    const float* bf3 = (const float*)d_in[13];
    float* out = (float*)d_out;

    const int B = in_sizes[0] / (NN * 12);
    const int E = in_sizes[1] / 2;

    prep_kernel<<<1, 256>>>(ei, E);

    static int smem_set = 0;
    if (!smem_set) {
        cudaFuncSetAttribute(gcn_fused_kernel,
                             cudaFuncAttributeMaxDynamicSharedMemorySize,
                             SM_BYTES);
        smem_set = 1;
    }

    const int blocks = (B + BT - 1) / BT;
    gcn_fused_kernel<<<blocks, THREADS, SM_BYTES>>>(
        x, W1, b1, W2, b2, W3, b3, Wf1, bf1, Wf2, bf2, Wf3, bf3,
        out, B);
}

// round 10
// speedup vs baseline: 1.5876x; 1.2413x over previous
#include <cuda_runtime.h>
#include <math.h>

#define NN 231
#define BT 8
#define THREADS 512
#define NWARP 16
#define MAXM 4096     // padded-to-4 edges <= 231*4 + 2079 ~ 3003

#define S1S 68    // t1 row stride: 64 data + 4 (bank rotate, 16B aligned)
#define S2S 36    // t2 row stride: 32 + 4
#define T3S 20    // t3 row stride: 16 + 4
#define XFS 476   // FC input stride per graph
#define H1S 124   // FC1 out stride
#define H2S 92    // FC2 out stride

// ---------------- persistent CSR built by prep kernel ----------------
__device__ int    g_row_ptr[NN + 1];
__device__ float2 g_csr_e[MAXM];    // (w, src-as-float-bits)

// =====================================================================
// Prep: deterministic CSR (stable counting sort by dst); each row padded
// to a multiple of 4 with (w=0, src=0) dummies.
// =====================================================================
__global__ void prep_kernel(const void* __restrict__ ei, int E) {
    __shared__ short s_src[2304];
    __shared__ short s_dst[2304];
    __shared__ int   deg[NN];
    __shared__ int   pdeg[NN];
    __shared__ int   rp[NN + 1];
    __shared__ float inv[NN];
    __shared__ int   cnt[32][NN];
    __shared__ int   is64;

    const int tid = threadIdx.x;
    const int M = E + NN;

    if (tid == 0) {
        const long long* p = (const long long*)ei;
        int ok = 1;
        for (int i = 0; i < 8; i++) {
            long long v = p[i];
            if (v < 0 || v >= NN) ok = 0;
        }
        is64 = ok;
    }
    for (int n = tid; n < NN; n += blockDim.x) deg[n] = 0;
    __syncthreads();

    for (int e = tid; e < M; e += blockDim.x) {
        int s, d;
        if (e < E) {
            if (is64) {
                s = (int)((const long long*)ei)[e];
                d = (int)((const long long*)ei)[E + e];
            } else {
                s = ((const int*)ei)[e];
                d = ((const int*)ei)[E + e];
            }
        } else {
            s = d = e - E;   // self loops appended after real edges
        }
        s_src[e] = (short)s;
        s_dst[e] = (short)d;
        atomicAdd(&deg[d], 1);
    }
    __syncthreads();

    for (int n = tid; n < NN; n += blockDim.x) {
        inv[n]  = rsqrtf((float)max(deg[n], 1));
        pdeg[n] = (deg[n] + 3) & ~3;
    }
    __syncthreads();
    if (tid == 0) {
        int acc = 0;
        for (int n = 0; n < NN; n++) { rp[n] = acc; acc += pdeg[n]; }
        rp[NN] = acc;
    }
    for (int i = tid; i < 32 * NN; i += blockDim.x)
        ((int*)cnt)[i] = 0;
    __syncthreads();

    const int chunk = (M + 31) / 32;
    if (tid < 32) {
        int e0 = tid * chunk, e1 = min(e0 + chunk, M);
        for (int e = e0; e < e1; e++) cnt[tid][s_dst[e]]++;
    }
    __syncthreads();

    for (int n = tid; n < NN; n += blockDim.x) {
        int run = rp[n];
        for (int t = 0; t < 32; t++) {
            int c = cnt[t][n];
            cnt[t][n] = run;
            run += c;
        }
    }
    __syncthreads();

    if (tid < 32) {
        int e0 = tid * chunk, e1 = min(e0 + chunk, M);
        for (int e = e0; e < e1; e++) {
            int d = s_dst[e], s = s_src[e];
            int pos = cnt[tid][d]++;
            g_csr_e[pos] = make_float2(inv[s] * inv[d], __int_as_float(s));
        }
    }
    __syncthreads();

    // pad rows with dummy edges (w=0, src=0)
    for (int n = tid; n < NN; n += blockDim.x) {
        for (int p = deg[n]; p < pdeg[n]; p++)
            g_csr_e[rp[n] + p] = make_float2(0.0f, __int_as_float(0));
    }
    for (int n = tid; n <= NN; n += blockDim.x) g_row_ptr[n] = rp[n];
}

// =====================================================================
__device__ __forceinline__ float htanh(float x) {
    float y;
    asm("tanh.approx.f32 %0, %1;" : "=f"(y) : "f"(x));
    return y;
}
__device__ __forceinline__ float elu1(float v) {
    return v > 0.0f ? v : (__expf(v) - 1.0f);
}

// small-weight shared offsets (floats)
#define O_W1  0      // 12x8
#define O_B1  96     // 8
#define O_W2  104    // 8x4
#define O_B2  136    // 4
#define O_W3  140    // 4x2
#define O_B3  148    // 2
#define O_BF1 152    // 120
#define O_BF2 272    // 84
#define O_BF3 356    // 10
#define SMALLSZ 384

#define SM_FLOATS (NN*S1S + NN*S2S + SMALLSZ)
#define SM_BYTES  (SM_FLOATS*4 + (NN+1)*4)

__global__ void __launch_bounds__(THREADS, 2)
gcn_fused_kernel(const float* __restrict__ x,
                 const float* __restrict__ W1, const float* __restrict__ b1,
                 const float* __restrict__ W2, const float* __restrict__ b2,
                 const float* __restrict__ W3, const float* __restrict__ b3,
                 const float* __restrict__ Wf1, const float* __restrict__ bf1,
                 const float* __restrict__ Wf2, const float* __restrict__ bf2,
                 const float* __restrict__ Wf3, const float* __restrict__ bf3,
                 float* __restrict__ out, int B) {
    extern __shared__ float sm[];
    float*  S1      = sm;                  // t1 [n][b8][f8], stride 68
    float*  S2      = S1 + NN * S1S;       // t2 [n][b8][f4], stride 36
    float*  s_small = S2 + NN * S2S;
    int*    s_rp    = (int*)(s_small + SMALLSZ);

    const int tid  = threadIdx.x;
    const int wid  = tid >> 5;
    const int lane = tid & 31;
    const int b0   = blockIdx.x * BT;

    // ---- stage rp + small weights ----
    for (int i = tid; i <= NN; i += THREADS) s_rp[i] = g_row_ptr[i];
    for (int i = tid; i < 96;  i += THREADS) s_small[O_W1 + i] = W1[i];
    for (int i = tid; i < 8;   i += THREADS) s_small[O_B1 + i] = b1[i];
    for (int i = tid; i < 32;  i += THREADS) s_small[O_W2 + i] = W2[i];
    for (int i = tid; i < 4;   i += THREADS) s_small[O_B2 + i] = b2[i];
    for (int i = tid; i < 8;   i += THREADS) s_small[O_W3 + i] = W3[i];
    for (int i = tid; i < 2;   i += THREADS) s_small[O_B3 + i] = b3[i];
    for (int i = tid; i < 120; i += THREADS) s_small[O_BF1 + i] = bf1[i];
    for (int i = tid; i < 84;  i += THREADS) s_small[O_BF2 + i] = bf2[i];
    for (int i = tid; i < 10;  i += THREADS) s_small[O_BF3 + i] = bf3[i];
    __syncthreads();

    // ========== T1: t1 = x @ W1 -> S1[n][b][f] ==========
    for (int idx = tid; idx < NN * BT; idx += THREADS) {
        const int b = idx / NN, n = idx - b * NN;
        const int g = b0 + b;
        float xa[12];
        if (g < B) {
            const float4* xp = (const float4*)(x + ((size_t)g * NN + n) * 12);
            float4 v0 = xp[0], v1 = xp[1], v2 = xp[2];
            xa[0] = v0.x; xa[1] = v0.y; xa[2]  = v0.z; xa[3]  = v0.w;
            xa[4] = v1.x; xa[5] = v1.y; xa[6]  = v1.z; xa[7]  = v1.w;
            xa[8] = v2.x; xa[9] = v2.y; xa[10] = v2.z; xa[11] = v2.w;
        } else {
            #pragma unroll
            for (int c = 0; c < 12; c++) xa[c] = 0.0f;
        }
        float t[8];
        #pragma unroll
        for (int f = 0; f < 8; f++) {
            float a = 0.0f;
            #pragma unroll
            for (int c = 0; c < 12; c++) a += xa[c] * s_small[O_W1 + c * 8 + f];
            t[f] = a;
        }
        float* dst = S1 + n * S1S + b * 8;
        *(float4*)dst       = make_float4(t[0], t[1], t[2], t[3]);
        *(float4*)(dst + 4) = make_float4(t[4], t[5], t[6], t[7]);
    }
    __syncthreads();

    // ========== A1: h1 = tanh(agg(t1)+b1); t2 = h1@W2 -> S2 ==========
    // half-warp per edge; lh owns float4: b = lh>>1, fq = (lh&1)*4
    {
        const int h  = lane >> 4;
        const int lh = lane & 15;
        const int fq = (lh & 1) * 4;
        float w2r[4][4];
        #pragma unroll
        for (int i = 0; i < 4; i++)
            #pragma unroll
            for (int f2 = 0; f2 < 4; f2++)
                w2r[i][f2] = s_small[O_W2 + (fq + i) * 4 + f2];
        const float4 b1v = *(const float4*)(s_small + O_B1 + fq);

        for (int n = wid; n < NN; n += NWARP) {
            const int j0 = s_rp[n], j1 = s_rp[n + 1];
            float4 acc = make_float4(0.f, 0.f, 0.f, 0.f);
            for (int j = j0; j < j1; j += 2) {
                const float2 e = __ldg(&g_csr_e[j + h]);
                const float4 v = *(const float4*)(S1 + __float_as_int(e.y) * S1S + lh * 4);
                acc.x += e.x * v.x; acc.y += e.x * v.y;
                acc.z += e.x * v.z; acc.w += e.x * v.w;
            }
            acc.x += __shfl_xor_sync(~0u, acc.x, 16);
            acc.y += __shfl_xor_sync(~0u, acc.y, 16);
            acc.z += __shfl_xor_sync(~0u, acc.z, 16);
            acc.w += __shfl_xor_sync(~0u, acc.w, 16);
            const float tx = htanh(acc.x + b1v.x);
            const float ty = htanh(acc.y + b1v.y);
            const float tz = htanh(acc.z + b1v.z);
            const float tw = htanh(acc.w + b1v.w);
            float4 p;
            p.x = tx * w2r[0][0] + ty * w2r[1][0] + tz * w2r[2][0] + tw * w2r[3][0];
            p.y = tx * w2r[0][1] + ty * w2r[1][1] + tz * w2r[2][1] + tw * w2r[3][1];
            p.z = tx * w2r[0][2] + ty * w2r[1][2] + tz * w2r[2][2] + tw * w2r[3][2];
            p.w = tx * w2r[0][3] + ty * w2r[1][3] + tz * w2r[2][3] + tw * w2r[3][3];
            p.x += __shfl_xor_sync(~0u, p.x, 1);
            p.y += __shfl_xor_sync(~0u, p.y, 1);
            p.z += __shfl_xor_sync(~0u, p.z, 1);
            p.w += __shfl_xor_sync(~0u, p.w, 1);
            if (lane < 16 && !(lane & 1))
                *(float4*)(S2 + n * S2S + (lh >> 1) * 4) = p;
        }
    }
    __syncthreads();

    // ========== A2: h2 = tanh(agg(t2)+b2); t3 = h2@W3 -> S1 (t3) =====
    // quarter-warp per edge; lb owns float4 (all 4 f of batch lb)
    {
        const int q  = lane >> 3;
        const int lb = lane & 7;
        const float4 b2v = *(const float4*)(s_small + O_B2);
        float w30[4], w31[4];
        #pragma unroll
        for (int f = 0; f < 4; f++) {
            w30[f] = s_small[O_W3 + f * 2 + 0];
            w31[f] = s_small[O_W3 + f * 2 + 1];
        }
        for (int n = wid; n < NN; n += NWARP) {
            const int j0 = s_rp[n], j1 = s_rp[n + 1];
            float4 acc = make_float4(0.f, 0.f, 0.f, 0.f);
            for (int j = j0; j < j1; j += 4) {
                const float2 e = __ldg(&g_csr_e[j + q]);
                const float4 v = *(const float4*)(S2 + __float_as_int(e.y) * S2S + lb * 4);
                acc.x += e.x * v.x; acc.y += e.x * v.y;
                acc.z += e.x * v.z; acc.w += e.x * v.w;
            }
            #pragma unroll
            for (int off = 8; off <= 16; off <<= 1) {
                acc.x += __shfl_xor_sync(~0u, acc.x, off);
                acc.y += __shfl_xor_sync(~0u, acc.y, off);
                acc.z += __shfl_xor_sync(~0u, acc.z, off);
                acc.w += __shfl_xor_sync(~0u, acc.w, off);
            }
            const float t0 = htanh(acc.x + b2v.x);
            const float t1 = htanh(acc.y + b2v.y);
            const float t2 = htanh(acc.z + b2v.z);
            const float t3 = htanh(acc.w + b2v.w);
            const float p0 = t0 * w30[0] + t1 * w30[1] + t2 * w30[2] + t3 * w30[3];
            const float p1 = t0 * w31[0] + t1 * w31[1] + t2 * w31[2] + t3 * w31[3];
            if (lane < 8)
                *(float2*)(S1 + n * T3S + lb * 2) = make_float2(p0, p1);
        }
    }
    __syncthreads();

    // ========== A3: h3 = agg(t3)+b3 -> xfc[b][2n+c] in S2 ============
    {
        const int o  = lane >> 3;
        const int lb = lane & 7;
        const float b3x = s_small[O_B3 + 0];
        const float b3y = s_small[O_B3 + 1];
        for (int n = wid; n < NN; n += NWARP) {
            const int j0 = s_rp[n], j1 = s_rp[n + 1];
            float ax = 0.0f, ay = 0.0f;
            for (int j = j0; j < j1; j += 4) {
                const float2 e = __ldg(&g_csr_e[j + o]);
                const float2 v = *(const float2*)(S1 + __float_as_int(e.y) * T3S + lb * 2);
                ax += e.x * v.x;
                ay += e.x * v.y;
            }
            #pragma unroll
            for (int off = 8; off <= 16; off <<= 1) {
                ax += __shfl_xor_sync(~0u, ax, off);
                ay += __shfl_xor_sync(~0u, ay, off);
            }
            if (lane < 8)
                *(float2*)(S2 + lb * XFS + 2 * n) = make_float2(ax + b3x, ay + b3y);
        }
        // zero xfc pad k = 462, 463 (read by the padded FC1 loop)
        if (tid < 16)
            S2[(tid >> 1) * XFS + 462 + (tid & 1)] = 0.0f;
    }
    __syncthreads();

    // ========== FC1: xfc[8,464] @ Wf1[462,120] + bf1 -> elu -> S1 ====
    // 480 active threads: kh (4 k-quarters of 116) x jg (60: 2 j) x bq (2: 4 b)
    {
        const int kh = tid >> 7;            // 0..3
        const int r  = tid & 127;           // 0..127
        const int jg = r >> 1;              // 0..63 (active < 60)
        const int bq = r & 1;
        const bool active = jg < 60;
        float acc[2][4];
        #pragma unroll
        for (int j = 0; j < 2; j++)
            #pragma unroll
            for (int i = 0; i < 4; i++) acc[j][i] = 0.0f;

        if (active) {
            const int j0 = jg * 2;
            const float* wb = Wf1 + j0;
            const float* x0 = S2 + (bq * 4 + 0) * XFS;
            const float* x1 = S2 + (bq * 4 + 1) * XFS;
            const float* x2 = S2 + (bq * 4 + 2) * XFS;
            const float* x3 = S2 + (bq * 4 + 3) * XFS;
            const int k0 = kh * 116;
            #pragma unroll 1
            for (int k = k0; k < k0 + 116; k += 4) {
                const float4 a0 = *(const float4*)(x0 + k);
                const float4 a1 = *(const float4*)(x1 + k);
                const float4 a2 = *(const float4*)(x2 + k);
                const float4 a3 = *(const float4*)(x3 + k);
                const float2 w0 = __ldg((const float2*)(wb + (k + 0) * 120));
                const float2 w1 = __ldg((const float2*)(wb + (k + 1) * 120));
                const float2 w2 = __ldg((const float2*)(wb + (k + 2) * 120));
                const float2 w3 = __ldg((const float2*)(wb + (k + 3) * 120));
                acc[0][0] += a0.x * w0.x + a0.y * w1.x + a0.z * w2.x + a0.w * w3.x;
                acc[1][0] += a0.x * w0.y + a0.y * w1.y + a0.z * w2.y + a0.w * w3.y;
                acc[0][1] += a1.x * w0.x + a1.y * w1.x + a1.z * w2.x + a1.w * w3.x;
                acc[1][1] += a1.x * w0.y + a1.y * w1.y + a1.z * w2.y + a1.w * w3.y;
                acc[0][2] += a2.x * w0.x + a2.y * w1.x + a2.z * w2.x + a2.w * w3.x;
                acc[1][2] += a2.x * w0.y + a2.y * w1.y + a2.z * w2.y + a2.w * w3.y;
                acc[0][3] += a3.x * w0.x + a3.y * w1.x + a3.z * w2.x + a3.w * w3.x;
                acc[1][3] += a3.x * w0.y + a3.y * w1.y + a3.z * w2.y + a3.w * w3.y;
            }
            if (kh > 0) {
                // write partials to dead S1 scratch (beyond h1 region)
                float* scr = S1 + 4096 + ((kh - 1) * 120 + r) * 8;
                *(float4*)scr = make_float4(acc[0][0], acc[1][0], acc[0][1], acc[1][1]);
                *(float4*)(scr + 4) = make_float4(acc[0][2], acc[1][2], acc[0][3], acc[1][3]);
            }
        }
        __syncthreads();
        if (active && kh == 0) {
            const int j0 = jg * 2;
            const float bfa = s_small[O_BF1 + j0];
            const float bfb = s_small[O_BF1 + j0 + 1];
            #pragma unroll
            for (int p = 0; p < 3; p++) {
                const float* scr = S1 + 4096 + (p * 120 + r) * 8;
                const float4 s0 = *(const float4*)scr;
                const float4 s1 = *(const float4*)(scr + 4);
                acc[0][0] += s0.x; acc[1][0] += s0.y;
                acc[0][1] += s0.z; acc[1][1] += s0.w;
                acc[0][2] += s1.x; acc[1][2] += s1.y;
                acc[0][3] += s1.z; acc[1][3] += s1.w;
            }
            const int bb = bq * 4;
            S1[(bb + 0) * H1S + j0]     = elu1(acc[0][0] + bfa);
            S1[(bb + 0) * H1S + j0 + 1] = elu1(acc[1][0] + bfb);
            S1[(bb + 1) * H1S + j0]     = elu1(acc[0][1] + bfa);
            S1[(bb + 1) * H1S + j0 + 1] = elu1(acc[1][1] + bfb);
            S1[(bb + 2) * H1S + j0]     = elu1(acc[0][2] + bfa);
            S1[(bb + 2) * H1S + j0 + 1] = elu1(acc[1][2] + bfb);
            S1[(bb + 3) * H1S + j0]     = elu1(acc[0][3] + bfa);
            S1[(bb + 3) * H1S + j0 + 1] = elu1(acc[1][3] + bfb);
        }
    }
    __syncthreads();

    // ========== FC2: h1[8,120] @ Wf2[120,84] + bf2 -> elu -> S2 ======
    if (tid < 336) {
        const int b = tid & 7, jg = tid >> 3;   // jg 0..41
        const int j0 = jg * 2;
        float2 acc = make_float2(s_small[O_BF2 + j0], s_small[O_BF2 + j0 + 1]);
        const float* xin = S1 + b * H1S;
        const float* wb  = Wf2 + j0;
        #pragma unroll 2
        for (int k = 0; k < 120; k += 4) {
            const float4 v  = *(const float4*)(xin + k);
            const float2 w0 = __ldg((const float2*)(wb + (k + 0) * 84));
            const float2 w1 = __ldg((const float2*)(wb + (k + 1) * 84));
            const float2 w2 = __ldg((const float2*)(wb + (k + 2) * 84));
            const float2 w3 = __ldg((const float2*)(wb + (k + 3) * 84));
            acc.x += v.x * w0.x + v.y * w1.x + v.z * w2.x + v.w * w3.x;
            acc.y += v.x * w0.y + v.y * w1.y + v.z * w2.y + v.w * w3.y;
        }
        S2[b * H2S + j0 + 0] = elu1(acc.x);
        S2[b * H2S + j0 + 1] = elu1(acc.y);
    }
    __syncthreads();

    // ========== FC3: h2[8,84] @ Wf3[84,10] + bf3 -> out ==============
    if (tid < 80) {
        const int b = tid & 7, j = tid >> 3;    // j 0..9
        float acc = s_small[O_BF3 + j];
        const float* xin = S2 + b * H2S;
        #pragma unroll 3
        for (int k = 0; k < 84; k += 4) {
            const float4 v = *(const float4*)(xin + k);
            acc += v.x * __ldg(Wf3 + (k + 0) * 10 + j);
            acc += v.y * __ldg(Wf3 + (k + 1) * 10 + j);
            acc += v.z * __ldg(Wf3 + (k + 2) * 10 + j);
            acc += v.w * __ldg(Wf3 + (k + 3) * 10 + j);
        }
        const int g = b0 + b;
        if (g < B) out[(size_t)g * 10 + j] = acc;
    }
}

// =====================================================================
extern "C" void kernel_launch(void* const* d_in, const int* in_sizes, int n_in,
                              void* d_out, int out_size) {
    const float* x   = (const float*)d_in[0];
    const void*  ei  = d_in[1];
    const float* W1  = (const float*)d_in[2];
    const float* b1  = (const float*)d_in[3];
    const float* W2  = (const float*)d_in[4];
    const float* b2  = (const float*)d_in[5];
    const float* W3  = (const float*)d_in[6];
    const float* b3  = (const float*)d_in[7];
    const float* Wf1 = (const float*)d_in[8];
    const float* bf1 = (const float*)d_in[9];
    const float* Wf2 = (const float*)d_in[10];
    const float* bf2 = (const float*)d_in[11];
    const float* Wf3 = (const float*)d_in[12];
    const float* bf3 = (const float*)d_in[13];
    float* out = (float*)d_out;

    const int B = in_sizes[0] / (NN * 12);
    const int E = in_sizes[1] / 2;

    prep_kernel<<<1, 256>>>(ei, E);

    static int smem_set = 0;
    if (!smem_set) {
        cudaFuncSetAttribute(gcn_fused_kernel,
                             cudaFuncAttributeMaxDynamicSharedMemorySize,
                             SM_BYTES);
        smem_set = 1;
    }

    const int blocks = (B + BT - 1) / BT;
    gcn_fused_kernel<<<blocks, THREADS, SM_BYTES>>>(
        x, W1, b1, W2, b2, W3, b3, Wf1, bf1, Wf2, bf2, Wf3, bf3,
        out, B);
}

// round 11
// speedup vs baseline: 1.6023x; 1.0092x over previous
#include <cuda_runtime.h>
#include <math.h>

#define NN 231
#define BT 8
#define THREADS 512
#define NWARP 16
#define MAXM 4096     // padded-to-4 edges <= 231*4 + 2079 ~ 3003

#define S1S 68    // t1 row stride: 64 data + 4 (bank rotate, 16B aligned)
#define S2S 36    // t2 row stride: 32 + 4
#define T3S 20    // t3 row stride: 16 + 4
#define XFS 476   // FC input stride per graph
#define H1S 124   // FC1 out stride
#define H2S 92    // FC2 out stride

typedef unsigned long long ull;

// ---------------- persistent CSR built by prep kernel ----------------
__device__ int    g_row_ptr[NN + 1];
__device__ float2 g_csr_e[MAXM];    // (w, src-as-float-bits)

// =====================================================================
// Prep: deterministic CSR (stable counting sort by dst); each row padded
// to a multiple of 4 with (w=0, src=0) dummies.
// =====================================================================
__global__ void prep_kernel(const void* __restrict__ ei, int E) {
    __shared__ short s_src[2304];
    __shared__ short s_dst[2304];
    __shared__ int   deg[NN];
    __shared__ int   pdeg[NN];
    __shared__ int   rp[NN + 1];
    __shared__ float inv[NN];
    __shared__ int   cnt[32][NN];
    __shared__ int   is64;

    const int tid = threadIdx.x;
    const int M = E + NN;

    if (tid == 0) {
        const long long* p = (const long long*)ei;
        int ok = 1;
        for (int i = 0; i < 8; i++) {
            long long v = p[i];
            if (v < 0 || v >= NN) ok = 0;
        }
        is64 = ok;
    }
    for (int n = tid; n < NN; n += blockDim.x) deg[n] = 0;
    __syncthreads();

    for (int e = tid; e < M; e += blockDim.x) {
        int s, d;
        if (e < E) {
            if (is64) {
                s = (int)((const long long*)ei)[e];
                d = (int)((const long long*)ei)[E + e];
            } else {
                s = ((const int*)ei)[e];
                d = ((const int*)ei)[E + e];
            }
        } else {
            s = d = e - E;   // self loops appended after real edges
        }
        s_src[e] = (short)s;
        s_dst[e] = (short)d;
        atomicAdd(&deg[d], 1);
    }
    __syncthreads();

    for (int n = tid; n < NN; n += blockDim.x) {
        inv[n]  = rsqrtf((float)max(deg[n], 1));
        pdeg[n] = (deg[n] + 3) & ~3;
    }
    __syncthreads();
    if (tid == 0) {
        int acc = 0;
        for (int n = 0; n < NN; n++) { rp[n] = acc; acc += pdeg[n]; }
        rp[NN] = acc;
    }
    for (int i = tid; i < 32 * NN; i += blockDim.x)
        ((int*)cnt)[i] = 0;
    __syncthreads();

    const int chunk = (M + 31) / 32;
    if (tid < 32) {
        int e0 = tid * chunk, e1 = min(e0 + chunk, M);
        for (int e = e0; e < e1; e++) cnt[tid][s_dst[e]]++;
    }
    __syncthreads();

    for (int n = tid; n < NN; n += blockDim.x) {
        int run = rp[n];
        for (int t = 0; t < 32; t++) {
            int c = cnt[t][n];
            cnt[t][n] = run;
            run += c;
        }
    }
    __syncthreads();

    if (tid < 32) {
        int e0 = tid * chunk, e1 = min(e0 + chunk, M);
        for (int e = e0; e < e1; e++) {
            int d = s_dst[e], s = s_src[e];
            int pos = cnt[tid][d]++;
            g_csr_e[pos] = make_float2(inv[s] * inv[d], __int_as_float(s));
        }
    }
    __syncthreads();

    // pad rows with dummy edges (w=0, src=0)
    for (int n = tid; n < NN; n += blockDim.x) {
        for (int p = deg[n]; p < pdeg[n]; p++)
            g_csr_e[rp[n] + p] = make_float2(0.0f, __int_as_float(0));
    }
    for (int n = tid; n <= NN; n += blockDim.x) g_row_ptr[n] = rp[n];
}

// =====================================================================
__device__ __forceinline__ float htanh(float x) {
    float y;
    asm("tanh.approx.f32 %0, %1;" : "=f"(y) : "f"(x));
    return y;
}
__device__ __forceinline__ float elu1(float v) {
    return v > 0.0f ? v : (__expf(v) - 1.0f);
}
__device__ __forceinline__ ull ffma2(ull a, ull b, ull c) {
    ull d;
    asm("fma.rn.f32x2 %0, %1, %2, %3;" : "=l"(d) : "l"(a), "l"(b), "l"(c));
    return d;
}
__device__ __forceinline__ ull bcast2(float x) {
    ull d;
    asm("mov.b64 %0, {%1, %1};" : "=l"(d) : "r"(__float_as_uint(x)));
    return d;
}
__device__ __forceinline__ float2 unpack2(ull d) {
    unsigned int lo, hi;
    asm("mov.b64 {%0, %1}, %2;" : "=r"(lo), "=r"(hi) : "l"(d));
    return make_float2(__int_as_float(lo), __int_as_float(hi));
}

// small-weight shared offsets (floats)
#define O_W1  0      // 12x8
#define O_B1  96     // 8
#define O_W2  104    // 8x4
#define O_B2  136    // 4
#define O_W3  140    // 4x2
#define O_B3  148    // 2
#define O_BF1 152    // 120
#define O_BF2 272    // 84
#define O_BF3 356    // 10
#define SMALLSZ 384

#define SM_FLOATS (NN*S1S + NN*S2S + SMALLSZ)
#define SM_BYTES  (SM_FLOATS*4 + (NN+1)*4)

__global__ void __launch_bounds__(THREADS, 2)
gcn_fused_kernel(const float* __restrict__ x,
                 const float* __restrict__ W1, const float* __restrict__ b1,
                 const float* __restrict__ W2, const float* __restrict__ b2,
                 const float* __restrict__ W3, const float* __restrict__ b3,
                 const float* __restrict__ Wf1, const float* __restrict__ bf1,
                 const float* __restrict__ Wf2, const float* __restrict__ bf2,
                 const float* __restrict__ Wf3, const float* __restrict__ bf3,
                 float* __restrict__ out, int B) {
    extern __shared__ float sm[];
    float*  S1      = sm;                  // t1 [n][b8][f8], stride 68
    float*  S2      = S1 + NN * S1S;       // t2 [n][b8][f4], stride 36
    float*  s_small = S2 + NN * S2S;
    int*    s_rp    = (int*)(s_small + SMALLSZ);

    const int tid  = threadIdx.x;
    const int wid  = tid >> 5;
    const int lane = tid & 31;
    const int b0   = blockIdx.x * BT;

    // ---- stage rp + small weights ----
    for (int i = tid; i <= NN; i += THREADS) s_rp[i] = g_row_ptr[i];
    for (int i = tid; i < 96;  i += THREADS) s_small[O_W1 + i] = W1[i];
    for (int i = tid; i < 8;   i += THREADS) s_small[O_B1 + i] = b1[i];
    for (int i = tid; i < 32;  i += THREADS) s_small[O_W2 + i] = W2[i];
    for (int i = tid; i < 4;   i += THREADS) s_small[O_B2 + i] = b2[i];
    for (int i = tid; i < 8;   i += THREADS) s_small[O_W3 + i] = W3[i];
    for (int i = tid; i < 2;   i += THREADS) s_small[O_B3 + i] = b3[i];
    for (int i = tid; i < 120; i += THREADS) s_small[O_BF1 + i] = bf1[i];
    for (int i = tid; i < 84;  i += THREADS) s_small[O_BF2 + i] = bf2[i];
    for (int i = tid; i < 10;  i += THREADS) s_small[O_BF3 + i] = bf3[i];
    __syncthreads();

    // ========== T1: t1 = x @ W1 -> S1[n][b][f]  (packed f32x2) =======
    for (int idx = tid; idx < NN * BT; idx += THREADS) {
        const int b = idx / NN, n = idx - b * NN;
        const int g = b0 + b;
        float xa[12];
        if (g < B) {
            const float4* xp = (const float4*)(x + ((size_t)g * NN + n) * 12);
            float4 v0 = xp[0], v1 = xp[1], v2 = xp[2];
            xa[0] = v0.x; xa[1] = v0.y; xa[2]  = v0.z; xa[3]  = v0.w;
            xa[4] = v1.x; xa[5] = v1.y; xa[6]  = v1.z; xa[7]  = v1.w;
            xa[8] = v2.x; xa[9] = v2.y; xa[10] = v2.z; xa[11] = v2.w;
        } else {
            #pragma unroll
            for (int c = 0; c < 12; c++) xa[c] = 0.0f;
        }
        ull p0 = 0, p1 = 0, p2 = 0, p3 = 0;
        #pragma unroll
        for (int c = 0; c < 12; c++) {
            const ull xb = bcast2(xa[c]);
            const ull* wrow = (const ull*)(s_small + O_W1 + c * 8);
            p0 = ffma2(xb, wrow[0], p0);
            p1 = ffma2(xb, wrow[1], p1);
            p2 = ffma2(xb, wrow[2], p2);
            p3 = ffma2(xb, wrow[3], p3);
        }
        float* dst = S1 + n * S1S + b * 8;
        *(ulonglong2*)dst       = make_ulonglong2(p0, p1);
        *(ulonglong2*)(dst + 4) = make_ulonglong2(p2, p3);
    }
    __syncthreads();

    // ========== A1: h1 = tanh(agg(t1)+b1); t2 = h1@W2 -> S2 ==========
    // half-warp per edge, 2 edges per lane per iter (rows padded to 4);
    // lh owns float4: b = lh>>1, fq = (lh&1)*4
    {
        const int h  = lane >> 4;
        const int lh = lane & 15;
        const int fq = (lh & 1) * 4;
        float w2r[4][4];
        #pragma unroll
        for (int i = 0; i < 4; i++)
            #pragma unroll
            for (int f2 = 0; f2 < 4; f2++)
                w2r[i][f2] = s_small[O_W2 + (fq + i) * 4 + f2];
        const float4 b1v = *(const float4*)(s_small + O_B1 + fq);
        const float* S1p = S1 + lh * 4;

        for (int n = wid; n < NN; n += NWARP) {
            const int j0 = s_rp[n], j1 = s_rp[n + 1];
            ull a01 = 0, a23 = 0;
            for (int j = j0; j < j1; j += 4) {
                const float2 e0 = __ldg(&g_csr_e[j + h]);
                const float2 e1 = __ldg(&g_csr_e[j + 2 + h]);
                const ulonglong2 v0 =
                    *(const ulonglong2*)(S1p + __float_as_int(e0.y) * S1S);
                const ulonglong2 v1 =
                    *(const ulonglong2*)(S1p + __float_as_int(e1.y) * S1S);
                const ull w0 = bcast2(e0.x);
                const ull w1 = bcast2(e1.x);
                a01 = ffma2(v0.x, w0, a01);
                a23 = ffma2(v0.y, w0, a23);
                a01 = ffma2(v1.x, w1, a01);
                a23 = ffma2(v1.y, w1, a23);
            }
            const float2 u0 = unpack2(a01), u1 = unpack2(a23);
            float ax = u0.x, ay = u0.y, az = u1.x, aw = u1.y;
            ax += __shfl_xor_sync(~0u, ax, 16);
            ay += __shfl_xor_sync(~0u, ay, 16);
            az += __shfl_xor_sync(~0u, az, 16);
            aw += __shfl_xor_sync(~0u, aw, 16);
            const float tx = htanh(ax + b1v.x);
            const float ty = htanh(ay + b1v.y);
            const float tz = htanh(az + b1v.z);
            const float tw = htanh(aw + b1v.w);
            float4 p;
            p.x = tx * w2r[0][0] + ty * w2r[1][0] + tz * w2r[2][0] + tw * w2r[3][0];
            p.y = tx * w2r[0][1] + ty * w2r[1][1] + tz * w2r[2][1] + tw * w2r[3][1];
            p.z = tx * w2r[0][2] + ty * w2r[1][2] + tz * w2r[2][2] + tw * w2r[3][2];
            p.w = tx * w2r[0][3] + ty * w2r[1][3] + tz * w2r[2][3] + tw * w2r[3][3];
            p.x += __shfl_xor_sync(~0u, p.x, 1);
            p.y += __shfl_xor_sync(~0u, p.y, 1);
            p.z += __shfl_xor_sync(~0u, p.z, 1);
            p.w += __shfl_xor_sync(~0u, p.w, 1);
            if (lane < 16 && !(lane & 1))
                *(float4*)(S2 + n * S2S + (lh >> 1) * 4) = p;
        }
    }
    __syncthreads();

    // ========== A2: h2 = tanh(agg(t2)+b2); t3 = h2@W3 -> S1 (t3) =====
    // quarter-warp per edge; lb owns float4 (all 4 f of batch lb), packed
    {
        const int q  = lane >> 3;
        const int lb = lane & 7;
        const float4 b2v = *(const float4*)(s_small + O_B2);
        float w30[4], w31[4];
        #pragma unroll
        for (int f = 0; f < 4; f++) {
            w30[f] = s_small[O_W3 + f * 2 + 0];
            w31[f] = s_small[O_W3 + f * 2 + 1];
        }
        const float* S2p = S2 + lb * 4;
        for (int n = wid; n < NN; n += NWARP) {
            const int j0 = s_rp[n], j1 = s_rp[n + 1];
            ull a01 = 0, a23 = 0;
            for (int j = j0; j < j1; j += 4) {
                const float2 e = __ldg(&g_csr_e[j + q]);
                const ulonglong2 v =
                    *(const ulonglong2*)(S2p + __float_as_int(e.y) * S2S);
                const ull ww = bcast2(e.x);
                a01 = ffma2(v.x, ww, a01);
                a23 = ffma2(v.y, ww, a23);
            }
            const float2 u0 = unpack2(a01), u1 = unpack2(a23);
            float ax = u0.x, ay = u0.y, az = u1.x, aw = u1.y;
            #pragma unroll
            for (int off = 8; off <= 16; off <<= 1) {
                ax += __shfl_xor_sync(~0u, ax, off);
                ay += __shfl_xor_sync(~0u, ay, off);
                az += __shfl_xor_sync(~0u, az, off);
                aw += __shfl_xor_sync(~0u, aw, off);
            }
            const float t0 = htanh(ax + b2v.x);
            const float t1 = htanh(ay + b2v.y);
            const float t2 = htanh(az + b2v.z);
            const float t3 = htanh(aw + b2v.w);
            const float p0 = t0 * w30[0] + t1 * w30[1] + t2 * w30[2] + t3 * w30[3];
            const float p1 = t0 * w31[0] + t1 * w31[1] + t2 * w31[2] + t3 * w31[3];
            if (lane < 8)
                *(float2*)(S1 + n * T3S + lb * 2) = make_float2(p0, p1);
        }
    }
    __syncthreads();

    // ========== A3: h3 = agg(t3)+b3 -> xfc[b][2n+c] in S2 ============
    {
        const int o  = lane >> 3;
        const int lb = lane & 7;
        const float b3x = s_small[O_B3 + 0];
        const float b3y = s_small[O_B3 + 1];
        const float* T3p = S1 + lb * 2;
        for (int n = wid; n < NN; n += NWARP) {
            const int j0 = s_rp[n], j1 = s_rp[n + 1];
            float ax = 0.0f, ay = 0.0f;
            for (int j = j0; j < j1; j += 4) {
                const float2 e = __ldg(&g_csr_e[j + o]);
                const float2 v = *(const float2*)(T3p + __float_as_int(e.y) * T3S);
                ax += e.x * v.x;
                ay += e.x * v.y;
            }
            #pragma unroll
            for (int off = 8; off <= 16; off <<= 1) {
                ax += __shfl_xor_sync(~0u, ax, off);
                ay += __shfl_xor_sync(~0u, ay, off);
            }
            if (lane < 8)
                *(float2*)(S2 + lb * XFS + 2 * n) = make_float2(ax + b3x, ay + b3y);
        }
        // zero xfc pad k = 462, 463 (read by the padded FC1 loop)
        if (tid < 16)
            S2[(tid >> 1) * XFS + 462 + (tid & 1)] = 0.0f;
    }
    __syncthreads();

    // ========== FC1: xfc[8,464] @ Wf1[462,120] + bf1 -> elu -> S1 ====
    // 480 active threads: kh (4 k-quarters of 116) x jg (60: 2 j) x bq (2: 4 b)
    {
        const int kh = tid >> 7;            // 0..3
        const int r  = tid & 127;           // 0..127
        const int jg = r >> 1;              // 0..63 (active < 60)
        const int bq = r & 1;
        const bool active = jg < 60;
        float acc[2][4];
        #pragma unroll
        for (int j = 0; j < 2; j++)
            #pragma unroll
            for (int i = 0; i < 4; i++) acc[j][i] = 0.0f;

        if (active) {
            const int j0 = jg * 2;
            const float* wb = Wf1 + j0;
            const float* x0 = S2 + (bq * 4 + 0) * XFS;
            const float* x1 = S2 + (bq * 4 + 1) * XFS;
            const float* x2 = S2 + (bq * 4 + 2) * XFS;
            const float* x3 = S2 + (bq * 4 + 3) * XFS;
            const int k0 = kh * 116;
            #pragma unroll 1
            for (int k = k0; k < k0 + 116; k += 4) {
                const float4 a0 = *(const float4*)(x0 + k);
                const float4 a1 = *(const float4*)(x1 + k);
                const float4 a2 = *(const float4*)(x2 + k);
                const float4 a3 = *(const float4*)(x3 + k);
                const float2 w0 = __ldg((const float2*)(wb + (k + 0) * 120));
                const float2 w1 = __ldg((const float2*)(wb + (k + 1) * 120));
                const float2 w2 = __ldg((const float2*)(wb + (k + 2) * 120));
                const float2 w3 = __ldg((const float2*)(wb + (k + 3) * 120));
                acc[0][0] += a0.x * w0.x + a0.y * w1.x + a0.z * w2.x + a0.w * w3.x;
                acc[1][0] += a0.x * w0.y + a0.y * w1.y + a0.z * w2.y + a0.w * w3.y;
                acc[0][1] += a1.x * w0.x + a1.y * w1.x + a1.z * w2.x + a1.w * w3.x;
                acc[1][1] += a1.x * w0.y + a1.y * w1.y + a1.z * w2.y + a1.w * w3.y;
                acc[0][2] += a2.x * w0.x + a2.y * w1.x + a2.z * w2.x + a2.w * w3.x;
                acc[1][2] += a2.x * w0.y + a2.y * w1.y + a2.z * w2.y + a2.w * w3.y;
                acc[0][3] += a3.x * w0.x + a3.y * w1.x + a3.z * w2.x + a3.w * w3.x;
                acc[1][3] += a3.x * w0.y + a3.y * w1.y + a3.z * w2.y + a3.w * w3.y;
            }
            if (kh > 0) {
                // write partials to dead S1 scratch (beyond h1 region)
                float* scr = S1 + 4096 + ((kh - 1) * 120 + r) * 8;
                *(float4*)scr = make_float4(acc[0][0], acc[1][0], acc[0][1], acc[1][1]);
                *(float4*)(scr + 4) = make_float4(acc[0][2], acc[1][2], acc[0][3], acc[1][3]);
            }
        }
        __syncthreads();
        if (active && kh == 0) {
            const int j0 = jg * 2;
            const float bfa = s_small[O_BF1 + j0];
            const float bfb = s_small[O_BF1 + j0 + 1];
            #pragma unroll
            for (int p = 0; p < 3; p++) {
                const float* scr = S1 + 4096 + (p * 120 + r) * 8;
                const float4 s0 = *(const float4*)scr;
                const float4 s1 = *(const float4*)(scr + 4);
                acc[0][0] += s0.x; acc[1][0] += s0.y;
                acc[0][1] += s0.z; acc[1][1] += s0.w;
                acc[0][2] += s1.x; acc[1][2] += s1.y;
                acc[0][3] += s1.z; acc[1][3] += s1.w;
            }
            const int bb = bq * 4;
            S1[(bb + 0) * H1S + j0]     = elu1(acc[0][0] + bfa);
            S1[(bb + 0) * H1S + j0 + 1] = elu1(acc[1][0] + bfb);
            S1[(bb + 1) * H1S + j0]     = elu1(acc[0][1] + bfa);
            S1[(bb + 1) * H1S + j0 + 1] = elu1(acc[1][1] + bfb);
            S1[(bb + 2) * H1S + j0]     = elu1(acc[0][2] + bfa);
            S1[(bb + 2) * H1S + j0 + 1] = elu1(acc[1][2] + bfb);
            S1[(bb + 3) * H1S + j0]     = elu1(acc[0][3] + bfa);
            S1[(bb + 3) * H1S + j0 + 1] = elu1(acc[1][3] + bfb);
        }
    }
    __syncthreads();

    // ========== FC2: h1[8,120] @ Wf2[120,84] + bf2 -> elu -> S2 ======
    if (tid < 336) {
        const int b = tid & 7, jg = tid >> 3;   // jg 0..41
        const int j0 = jg * 2;
        float2 acc = make_float2(s_small[O_BF2 + j0], s_small[O_BF2 + j0 + 1]);
        const float* xin = S1 + b * H1S;
        const float* wb  = Wf2 + j0;
        #pragma unroll 2
        for (int k = 0; k < 120; k += 4) {
            const float4 v  = *(const float4*)(xin + k);
            const float2 w0 = __ldg((const float2*)(wb + (k + 0) * 84));
            const float2 w1 = __ldg((const float2*)(wb + (k + 1) * 84));
            const float2 w2 = __ldg((const float2*)(wb + (k + 2) * 84));
            const float2 w3 = __ldg((const float2*)(wb + (k + 3) * 84));
            acc.x += v.x * w0.x + v.y * w1.x + v.z * w2.x + v.w * w3.x;
            acc.y += v.x * w0.y + v.y * w1.y + v.z * w2.y + v.w * w3.y;
        }
        S2[b * H2S + j0 + 0] = elu1(acc.x);
        S2[b * H2S + j0 + 1] = elu1(acc.y);
    }
    __syncthreads();

    // ========== FC3: h2[8,84] @ Wf3[84,10] + bf3 -> out ==============
    if (tid < 80) {
        const int b = tid & 7, j = tid >> 3;    // j 0..9
        float acc = s_small[O_BF3 + j];
        const float* xin = S2 + b * H2S;
        #pragma unroll 3
        for (int k = 0; k < 84; k += 4) {
            const float4 v = *(const float4*)(xin + k);
            acc += v.x * __ldg(Wf3 + (k + 0) * 10 + j);
            acc += v.y * __ldg(Wf3 + (k + 1) * 10 + j);
            acc += v.z * __ldg(Wf3 + (k + 2) * 10 + j);
            acc += v.w * __ldg(Wf3 + (k + 3) * 10 + j);
        }
        const int g = b0 + b;
        if (g < B) out[(size_t)g * 10 + j] = acc;
    }
}

// =====================================================================
extern "C" void kernel_launch(void* const* d_in, const int* in_sizes, int n_in,
                              void* d_out, int out_size) {
    const float* x   = (const float*)d_in[0];
    const void*  ei  = d_in[1];
    const float* W1  = (const float*)d_in[2];
    const float* b1  = (const float*)d_in[3];
    const float* W2  = (const float*)d_in[4];
    const float* b2  = (const float*)d_in[5];
    const float* W3  = (const float*)d_in[6];
    const float* b3  = (const float*)d_in[7];
    const float* Wf1 = (const float*)d_in[8];
    const float* bf1 = (const float*)d_in[9];
    const float* Wf2 = (const float*)d_in[10];
    const float* bf2 = (const float*)d_in[11];
    const float* Wf3 = (const float*)d_in[12];
    const float* bf3 = (const float*)d_in[13];
    float* out = (float*)d_out;

    const int B = in_sizes[0] / (NN * 12);
    const int E = in_sizes[1] / 2;

    prep_kernel<<<1, 256>>>(ei, E);

    static int smem_set = 0;
    if (!smem_set) {
        cudaFuncSetAttribute(gcn_fused_kernel,
                             cudaFuncAttributeMaxDynamicSharedMemorySize,
                             SM_BYTES);
        smem_set = 1;
    }

    const int blocks = (B + BT - 1) / BT;
    gcn_fused_kernel<<<blocks, THREADS, SM_BYTES>>>(
        x, W1, b1, W2, b2, W3, b3, Wf1, bf1, Wf2, bf2, Wf3, bf3,
        out, B);
}

// round 12
// speedup vs baseline: 1.6355x; 1.0207x over previous
#include <cuda_runtime.h>
#include <math.h>

#define NN 231
#define BT 8
#define THREADS 512
#define NWARP 16
#define MAXM 4096     // padded-to-4 edges <= 231*4 + 2079 ~ 3003

#define S1S 68    // t1 row stride: 64 data + 4 (bank rotate, 16B aligned)
#define S2S 36    // t2 row stride: 32 + 4
#define T3S 20    // t3 row stride: 16 + 4
#define XFS 476   // FC input stride per graph
#define H1S 124   // FC1 out stride
#define H2S 92    // FC2 out stride

typedef unsigned long long ull;

// ---------------- persistent CSR built by prep kernel ----------------
__device__ int    g_row_ptr[NN + 1];
__device__ float2 g_csr_e[MAXM];    // (w, src-as-float-bits)

// =====================================================================
// Prep: deterministic CSR (stable counting sort by dst); each row padded
// to a multiple of 4 with (w=0, src=0) dummies.
// =====================================================================
__global__ void prep_kernel(const void* __restrict__ ei, int E) {
    __shared__ short s_src[2304];
    __shared__ short s_dst[2304];
    __shared__ int   deg[NN];
    __shared__ int   pdeg[NN];
    __shared__ int   rp[NN + 1];
    __shared__ float inv[NN];
    __shared__ int   cnt[32][NN];
    __shared__ int   is64;

    const int tid = threadIdx.x;
    const int M = E + NN;

    if (tid == 0) {
        const long long* p = (const long long*)ei;
        int ok = 1;
        for (int i = 0; i < 8; i++) {
            long long v = p[i];
            if (v < 0 || v >= NN) ok = 0;
        }
        is64 = ok;
    }
    for (int n = tid; n < NN; n += blockDim.x) deg[n] = 0;
    __syncthreads();

    for (int e = tid; e < M; e += blockDim.x) {
        int s, d;
        if (e < E) {
            if (is64) {
                s = (int)((const long long*)ei)[e];
                d = (int)((const long long*)ei)[E + e];
            } else {
                s = ((const int*)ei)[e];
                d = ((const int*)ei)[E + e];
            }
        } else {
            s = d = e - E;   // self loops appended after real edges
        }
        s_src[e] = (short)s;
        s_dst[e] = (short)d;
        atomicAdd(&deg[d], 1);
    }
    __syncthreads();

    for (int n = tid; n < NN; n += blockDim.x) {
        inv[n]  = rsqrtf((float)max(deg[n], 1));
        pdeg[n] = (deg[n] + 3) & ~3;
    }
    __syncthreads();
    if (tid == 0) {
        int acc = 0;
        for (int n = 0; n < NN; n++) { rp[n] = acc; acc += pdeg[n]; }
        rp[NN] = acc;
    }
    for (int i = tid; i < 32 * NN; i += blockDim.x)
        ((int*)cnt)[i] = 0;
    __syncthreads();

    const int chunk = (M + 31) / 32;
    if (tid < 32) {
        int e0 = tid * chunk, e1 = min(e0 + chunk, M);
        for (int e = e0; e < e1; e++) cnt[tid][s_dst[e]]++;
    }
    __syncthreads();

    for (int n = tid; n < NN; n += blockDim.x) {
        int run = rp[n];
        for (int t = 0; t < 32; t++) {
            int c = cnt[t][n];
            cnt[t][n] = run;
            run += c;
        }
    }
    __syncthreads();

    if (tid < 32) {
        int e0 = tid * chunk, e1 = min(e0 + chunk, M);
        for (int e = e0; e < e1; e++) {
            int d = s_dst[e], s = s_src[e];
            int pos = cnt[tid][d]++;
            g_csr_e[pos] = make_float2(inv[s] * inv[d], __int_as_float(s));
        }
    }
    __syncthreads();

    // pad rows with dummy edges (w=0, src=0)
    for (int n = tid; n < NN; n += blockDim.x) {
        for (int p = deg[n]; p < pdeg[n]; p++)
            g_csr_e[rp[n] + p] = make_float2(0.0f, __int_as_float(0));
    }
    for (int n = tid; n <= NN; n += blockDim.x) g_row_ptr[n] = rp[n];
}

// =====================================================================
__device__ __forceinline__ float htanh(float x) {
    float y;
    asm("tanh.approx.f32 %0, %1;" : "=f"(y) : "f"(x));
    return y;
}
__device__ __forceinline__ float elu1(float v) {
    return v > 0.0f ? v : (__expf(v) - 1.0f);
}
__device__ __forceinline__ ull ffma2(ull a, ull b, ull c) {
    ull d;
    asm("fma.rn.f32x2 %0, %1, %2, %3;" : "=l"(d) : "l"(a), "l"(b), "l"(c));
    return d;
}
__device__ __forceinline__ ull bcast2(float x) {
    ull d;
    asm("mov.b64 %0, {%1, %1};" : "=l"(d) : "r"(__float_as_uint(x)));
    return d;
}
__device__ __forceinline__ float2 unpack2(ull d) {
    unsigned int lo, hi;
    asm("mov.b64 {%0, %1}, %2;" : "=r"(lo), "=r"(hi) : "l"(d));
    return make_float2(__int_as_float(lo), __int_as_float(hi));
}

// small-weight shared offsets (floats)
#define O_W1  0      // 12x8
#define O_B1  96     // 8
#define O_W2  104    // 8x4
#define O_B2  136    // 4
#define O_W3  140    // 4x2
#define O_B3  148    // 2
#define O_BF1 152    // 120
#define O_BF2 272    // 84
#define O_BF3 356    // 10
#define SMALLSZ 384

#define SM_FLOATS (NN*S1S + NN*S2S + SMALLSZ)
#define SM_BYTES  (SM_FLOATS*4 + (NN+1)*4)

__global__ void __launch_bounds__(THREADS, 2)
gcn_fused_kernel(const float* __restrict__ x,
                 const float* __restrict__ W1, const float* __restrict__ b1,
                 const float* __restrict__ W2, const float* __restrict__ b2,
                 const float* __restrict__ W3, const float* __restrict__ b3,
                 const float* __restrict__ Wf1, const float* __restrict__ bf1,
                 const float* __restrict__ Wf2, const float* __restrict__ bf2,
                 const float* __restrict__ Wf3, const float* __restrict__ bf3,
                 float* __restrict__ out, int B) {
    extern __shared__ float sm[];
    float*  S1      = sm;                  // t1 [n][b8][f8], stride 68
    float*  S2      = S1 + NN * S1S;       // t2 [n][b8][f4], stride 36
    float*  s_small = S2 + NN * S2S;
    int*    s_rp    = (int*)(s_small + SMALLSZ);

    const int tid  = threadIdx.x;
    const int wid  = tid >> 5;
    const int lane = tid & 31;
    const int b0   = blockIdx.x * BT;

    // ---- stage rp + small weights ----
    for (int i = tid; i <= NN; i += THREADS) s_rp[i] = g_row_ptr[i];
    for (int i = tid; i < 96;  i += THREADS) s_small[O_W1 + i] = W1[i];
    for (int i = tid; i < 8;   i += THREADS) s_small[O_B1 + i] = b1[i];
    for (int i = tid; i < 32;  i += THREADS) s_small[O_W2 + i] = W2[i];
    for (int i = tid; i < 4;   i += THREADS) s_small[O_B2 + i] = b2[i];
    for (int i = tid; i < 8;   i += THREADS) s_small[O_W3 + i] = W3[i];
    for (int i = tid; i < 2;   i += THREADS) s_small[O_B3 + i] = b3[i];
    for (int i = tid; i < 120; i += THREADS) s_small[O_BF1 + i] = bf1[i];
    for (int i = tid; i < 84;  i += THREADS) s_small[O_BF2 + i] = bf2[i];
    for (int i = tid; i < 10;  i += THREADS) s_small[O_BF3 + i] = bf3[i];
    __syncthreads();

    // ========== T1: t1 = x @ W1 -> S1[n][b][f]  (packed f32x2) =======
    for (int idx = tid; idx < NN * BT; idx += THREADS) {
        const int b = idx / NN, n = idx - b * NN;
        const int g = b0 + b;
        float xa[12];
        if (g < B) {
            const float4* xp = (const float4*)(x + ((size_t)g * NN + n) * 12);
            float4 v0 = xp[0], v1 = xp[1], v2 = xp[2];
            xa[0] = v0.x; xa[1] = v0.y; xa[2]  = v0.z; xa[3]  = v0.w;
            xa[4] = v1.x; xa[5] = v1.y; xa[6]  = v1.z; xa[7]  = v1.w;
            xa[8] = v2.x; xa[9] = v2.y; xa[10] = v2.z; xa[11] = v2.w;
        } else {
            #pragma unroll
            for (int c = 0; c < 12; c++) xa[c] = 0.0f;
        }
        ull p0 = 0, p1 = 0, p2 = 0, p3 = 0;
        #pragma unroll
        for (int c = 0; c < 12; c++) {
            const ull xb = bcast2(xa[c]);
            const ull* wrow = (const ull*)(s_small + O_W1 + c * 8);
            p0 = ffma2(xb, wrow[0], p0);
            p1 = ffma2(xb, wrow[1], p1);
            p2 = ffma2(xb, wrow[2], p2);
            p3 = ffma2(xb, wrow[3], p3);
        }
        float* dst = S1 + n * S1S + b * 8;
        *(ulonglong2*)dst       = make_ulonglong2(p0, p1);
        *(ulonglong2*)(dst + 4) = make_ulonglong2(p2, p3);
    }
    __syncthreads();

    // ========== A1: h1 = tanh(agg(t1)+b1); t2 = h1@W2 -> S2 ==========
    // half-warp per edge, 2 edges per lane per iter, SW-pipelined edge
    // prefetch; lh owns float4: b = lh>>1, fq = (lh&1)*4
    {
        const int h  = lane >> 4;
        const int lh = lane & 15;
        const int fq = (lh & 1) * 4;
        float w2r[4][4];
        #pragma unroll
        for (int i = 0; i < 4; i++)
            #pragma unroll
            for (int f2 = 0; f2 < 4; f2++)
                w2r[i][f2] = s_small[O_W2 + (fq + i) * 4 + f2];
        const float4 b1v = *(const float4*)(s_small + O_B1 + fq);
        const float* S1p = S1 + lh * 4;

        for (int n = wid; n < NN; n += NWARP) {
            const int j0 = s_rp[n], j1 = s_rp[n + 1];
            ull a01 = 0, a23 = 0;
            float2 e0 = __ldg(&g_csr_e[j0 + h]);
            float2 e1 = __ldg(&g_csr_e[j0 + 2 + h]);
            int j = j0;
            #pragma unroll 1
            for (; j + 4 < j1; j += 4) {
                const float2 f0 = __ldg(&g_csr_e[j + 4 + h]);
                const float2 f1 = __ldg(&g_csr_e[j + 6 + h]);
                const ulonglong2 v0 =
                    *(const ulonglong2*)(S1p + __float_as_int(e0.y) * S1S);
                const ulonglong2 v1 =
                    *(const ulonglong2*)(S1p + __float_as_int(e1.y) * S1S);
                const ull w0 = bcast2(e0.x);
                const ull w1 = bcast2(e1.x);
                a01 = ffma2(v0.x, w0, a01);
                a23 = ffma2(v0.y, w0, a23);
                a01 = ffma2(v1.x, w1, a01);
                a23 = ffma2(v1.y, w1, a23);
                e0 = f0; e1 = f1;
            }
            {   // tail (last 4 edges)
                const ulonglong2 v0 =
                    *(const ulonglong2*)(S1p + __float_as_int(e0.y) * S1S);
                const ulonglong2 v1 =
                    *(const ulonglong2*)(S1p + __float_as_int(e1.y) * S1S);
                const ull w0 = bcast2(e0.x);
                const ull w1 = bcast2(e1.x);
                a01 = ffma2(v0.x, w0, a01);
                a23 = ffma2(v0.y, w0, a23);
                a01 = ffma2(v1.x, w1, a01);
                a23 = ffma2(v1.y, w1, a23);
            }
            const float2 u0 = unpack2(a01), u1 = unpack2(a23);
            float ax = u0.x, ay = u0.y, az = u1.x, aw = u1.y;
            ax += __shfl_xor_sync(~0u, ax, 16);
            ay += __shfl_xor_sync(~0u, ay, 16);
            az += __shfl_xor_sync(~0u, az, 16);
            aw += __shfl_xor_sync(~0u, aw, 16);
            const float tx = htanh(ax + b1v.x);
            const float ty = htanh(ay + b1v.y);
            const float tz = htanh(az + b1v.z);
            const float tw = htanh(aw + b1v.w);
            float4 p;
            p.x = tx * w2r[0][0] + ty * w2r[1][0] + tz * w2r[2][0] + tw * w2r[3][0];
            p.y = tx * w2r[0][1] + ty * w2r[1][1] + tz * w2r[2][1] + tw * w2r[3][1];
            p.z = tx * w2r[0][2] + ty * w2r[1][2] + tz * w2r[2][2] + tw * w2r[3][2];
            p.w = tx * w2r[0][3] + ty * w2r[1][3] + tz * w2r[2][3] + tw * w2r[3][3];
            p.x += __shfl_xor_sync(~0u, p.x, 1);
            p.y += __shfl_xor_sync(~0u, p.y, 1);
            p.z += __shfl_xor_sync(~0u, p.z, 1);
            p.w += __shfl_xor_sync(~0u, p.w, 1);
            if (lane < 16 && !(lane & 1))
                *(float4*)(S2 + n * S2S + (lh >> 1) * 4) = p;
        }
    }
    __syncthreads();

    // ========== A2: h2 = tanh(agg(t2)+b2); t3 = h2@W3 -> S1 (t3) =====
    // quarter-warp per edge; lb owns float4, SW-pipelined edge prefetch
    {
        const int q  = lane >> 3;
        const int lb = lane & 7;
        const float4 b2v = *(const float4*)(s_small + O_B2);
        float w30[4], w31[4];
        #pragma unroll
        for (int f = 0; f < 4; f++) {
            w30[f] = s_small[O_W3 + f * 2 + 0];
            w31[f] = s_small[O_W3 + f * 2 + 1];
        }
        const float* S2p = S2 + lb * 4;
        for (int n = wid; n < NN; n += NWARP) {
            const int j0 = s_rp[n], j1 = s_rp[n + 1];
            ull a01 = 0, a23 = 0;
            float2 e = __ldg(&g_csr_e[j0 + q]);
            int j = j0;
            #pragma unroll 1
            for (; j + 4 < j1; j += 4) {
                const float2 f = __ldg(&g_csr_e[j + 4 + q]);
                const ulonglong2 v =
                    *(const ulonglong2*)(S2p + __float_as_int(e.y) * S2S);
                const ull ww = bcast2(e.x);
                a01 = ffma2(v.x, ww, a01);
                a23 = ffma2(v.y, ww, a23);
                e = f;
            }
            {   // tail
                const ulonglong2 v =
                    *(const ulonglong2*)(S2p + __float_as_int(e.y) * S2S);
                const ull ww = bcast2(e.x);
                a01 = ffma2(v.x, ww, a01);
                a23 = ffma2(v.y, ww, a23);
            }
            const float2 u0 = unpack2(a01), u1 = unpack2(a23);
            float ax = u0.x, ay = u0.y, az = u1.x, aw = u1.y;
            #pragma unroll
            for (int off = 8; off <= 16; off <<= 1) {
                ax += __shfl_xor_sync(~0u, ax, off);
                ay += __shfl_xor_sync(~0u, ay, off);
                az += __shfl_xor_sync(~0u, az, off);
                aw += __shfl_xor_sync(~0u, aw, off);
            }
            const float t0 = htanh(ax + b2v.x);
            const float t1 = htanh(ay + b2v.y);
            const float t2 = htanh(az + b2v.z);
            const float t3 = htanh(aw + b2v.w);
            const float p0 = t0 * w30[0] + t1 * w30[1] + t2 * w30[2] + t3 * w30[3];
            const float p1 = t0 * w31[0] + t1 * w31[1] + t2 * w31[2] + t3 * w31[3];
            if (lane < 8)
                *(float2*)(S1 + n * T3S + lb * 2) = make_float2(p0, p1);
        }
    }
    __syncthreads();

    // ========== A3: h3 = agg(t3)+b3 -> xfc[b][2n+c] in S2 ============
    {
        const int o  = lane >> 3;
        const int lb = lane & 7;
        const float b3x = s_small[O_B3 + 0];
        const float b3y = s_small[O_B3 + 1];
        const float* T3p = S1 + lb * 2;
        for (int n = wid; n < NN; n += NWARP) {
            const int j0 = s_rp[n], j1 = s_rp[n + 1];
            float ax = 0.0f, ay = 0.0f;
            float2 e = __ldg(&g_csr_e[j0 + o]);
            int j = j0;
            #pragma unroll 1
            for (; j + 4 < j1; j += 4) {
                const float2 f = __ldg(&g_csr_e[j + 4 + o]);
                const float2 v = *(const float2*)(T3p + __float_as_int(e.y) * T3S);
                ax += e.x * v.x;
                ay += e.x * v.y;
                e = f;
            }
            {   // tail
                const float2 v = *(const float2*)(T3p + __float_as_int(e.y) * T3S);
                ax += e.x * v.x;
                ay += e.x * v.y;
            }
            #pragma unroll
            for (int off = 8; off <= 16; off <<= 1) {
                ax += __shfl_xor_sync(~0u, ax, off);
                ay += __shfl_xor_sync(~0u, ay, off);
            }
            if (lane < 8)
                *(float2*)(S2 + lb * XFS + 2 * n) = make_float2(ax + b3x, ay + b3y);
        }
        // zero xfc pad k = 462, 463 (read by the padded FC1 loop)
        if (tid < 16)
            S2[(tid >> 1) * XFS + 462 + (tid & 1)] = 0.0f;
    }
    __syncthreads();

    // ========== FC1: xfc[8,464] @ Wf1[462,120] + bf1 -> elu -> S1 ====
    // 480 active threads: kh (4 k-quarters of 116) x jg (60: 2 j) x bq (2: 4 b)
    {
        const int kh = tid >> 7;            // 0..3
        const int r  = tid & 127;           // 0..127
        const int jg = r >> 1;              // 0..63 (active < 60)
        const int bq = r & 1;
        const bool active = jg < 60;
        float acc[2][4];
        #pragma unroll
        for (int j = 0; j < 2; j++)
            #pragma unroll
            for (int i = 0; i < 4; i++) acc[j][i] = 0.0f;

        if (active) {
            const int j0 = jg * 2;
            const float* wb = Wf1 + j0;
            const float* x0 = S2 + (bq * 4 + 0) * XFS;
            const float* x1 = S2 + (bq * 4 + 1) * XFS;
            const float* x2 = S2 + (bq * 4 + 2) * XFS;
            const float* x3 = S2 + (bq * 4 + 3) * XFS;
            const int k0 = kh * 116;
            #pragma unroll 1
            for (int k = k0; k < k0 + 116; k += 4) {
                const float4 a0 = *(const float4*)(x0 + k);
                const float4 a1 = *(const float4*)(x1 + k);
                const float4 a2 = *(const float4*)(x2 + k);
                const float4 a3 = *(const float4*)(x3 + k);
                const float2 w0 = __ldg((const float2*)(wb + (k + 0) * 120));
                const float2 w1 = __ldg((const float2*)(wb + (k + 1) * 120));
                const float2 w2 = __ldg((const float2*)(wb + (k + 2) * 120));
                const float2 w3 = __ldg((const float2*)(wb + (k + 3) * 120));
                acc[0][0] += a0.x * w0.x + a0.y * w1.x + a0.z * w2.x + a0.w * w3.x;
                acc[1][0] += a0.x * w0.y + a0.y * w1.y + a0.z * w2.y + a0.w * w3.y;
                acc[0][1] += a1.x * w0.x + a1.y * w1.x + a1.z * w2.x + a1.w * w3.x;
                acc[1][1] += a1.x * w0.y + a1.y * w1.y + a1.z * w2.y + a1.w * w3.y;
                acc[0][2] += a2.x * w0.x + a2.y * w1.x + a2.z * w2.x + a2.w * w3.x;
                acc[1][2] += a2.x * w0.y + a2.y * w1.y + a2.z * w2.y + a2.w * w3.y;
                acc[0][3] += a3.x * w0.x + a3.y * w1.x + a3.z * w2.x + a3.w * w3.x;
                acc[1][3] += a3.x * w0.y + a3.y * w1.y + a3.z * w2.y + a3.w * w3.y;
            }
            if (kh > 0) {
                // write partials to dead S1 scratch (beyond h1 region)
                float* scr = S1 + 4096 + ((kh - 1) * 120 + r) * 8;
                *(float4*)scr = make_float4(acc[0][0], acc[1][0], acc[0][1], acc[1][1]);
                *(float4*)(scr + 4) = make_float4(acc[0][2], acc[1][2], acc[0][3], acc[1][3]);
            }
        }
        __syncthreads();
        if (active && kh == 0) {
            const int j0 = jg * 2;
            const float bfa = s_small[O_BF1 + j0];
            const float bfb = s_small[O_BF1 + j0 + 1];
            #pragma unroll
            for (int p = 0; p < 3; p++) {
                const float* scr = S1 + 4096 + (p * 120 + r) * 8;
                const float4 s0 = *(const float4*)scr;
                const float4 s1 = *(const float4*)(scr + 4);
                acc[0][0] += s0.x; acc[1][0] += s0.y;
                acc[0][1] += s0.z; acc[1][1] += s0.w;
                acc[0][2] += s1.x; acc[1][2] += s1.y;
                acc[0][3] += s1.z; acc[1][3] += s1.w;
            }
            const int bb = bq * 4;
            S1[(bb + 0) * H1S + j0]     = elu1(acc[0][0] + bfa);
            S1[(bb + 0) * H1S + j0 + 1] = elu1(acc[1][0] + bfb);
            S1[(bb + 1) * H1S + j0]     = elu1(acc[0][1] + bfa);
            S1[(bb + 1) * H1S + j0 + 1] = elu1(acc[1][1] + bfb);
            S1[(bb + 2) * H1S + j0]     = elu1(acc[0][2] + bfa);
            S1[(bb + 2) * H1S + j0 + 1] = elu1(acc[1][2] + bfb);
            S1[(bb + 3) * H1S + j0]     = elu1(acc[0][3] + bfa);
            S1[(bb + 3) * H1S + j0 + 1] = elu1(acc[1][3] + bfb);
        }
    }
    __syncthreads();

    // ========== FC2: h1[8,120] @ Wf2[120,84] + bf2 -> elu -> S2 ======
    if (tid < 336) {
        const int b = tid & 7, jg = tid >> 3;   // jg 0..41
        const int j0 = jg * 2;
        float2 acc = make_float2(s_small[O_BF2 + j0], s_small[O_BF2 + j0 + 1]);
        const float* xin = S1 + b * H1S;
        const float* wb  = Wf2 + j0;
        #pragma unroll 2
        for (int k = 0; k < 120; k += 4) {
            const float4 v  = *(const float4*)(xin + k);
            const float2 w0 = __ldg((const float2*)(wb + (k + 0) * 84));
            const float2 w1 = __ldg((const float2*)(wb + (k + 1) * 84));
            const float2 w2 = __ldg((const float2*)(wb + (k + 2) * 84));
            const float2 w3 = __ldg((const float2*)(wb + (k + 3) * 84));
            acc.x += v.x * w0.x + v.y * w1.x + v.z * w2.x + v.w * w3.x;
            acc.y += v.x * w0.y + v.y * w1.y + v.z * w2.y + v.w * w3.y;
        }
        S2[b * H2S + j0 + 0] = elu1(acc.x);
        S2[b * H2S + j0 + 1] = elu1(acc.y);
    }
    __syncthreads();

    // ========== FC3: h2[8,84] @ Wf3[84,10] + bf3 -> out ==============
    if (tid < 80) {
        const int b = tid & 7, j = tid >> 3;    // j 0..9
        float acc = s_small[O_BF3 + j];
        const float* xin = S2 + b * H2S;
        #pragma unroll 3
        for (int k = 0; k < 84; k += 4) {
            const float4 v = *(const float4*)(xin + k);
            acc += v.x * __ldg(Wf3 + (k + 0) * 10 + j);
            acc += v.y * __ldg(Wf3 + (k + 1) * 10 + j);
            acc += v.z * __ldg(Wf3 + (k + 2) * 10 + j);
            acc += v.w * __ldg(Wf3 + (k + 3) * 10 + j);
        }
        const int g = b0 + b;
        if (g < B) out[(size_t)g * 10 + j] = acc;
    }
}

// =====================================================================
extern "C" void kernel_launch(void* const* d_in, const int* in_sizes, int n_in,
                              void* d_out, int out_size) {
    const float* x   = (const float*)d_in[0];
    const void*  ei  = d_in[1];
    const float* W1  = (const float*)d_in[2];
    const float* b1  = (const float*)d_in[3];
    const float* W2  = (const float*)d_in[4];
    const float* b2  = (const float*)d_in[5];
    const float* W3  = (const float*)d_in[6];
    const float* b3  = (const float*)d_in[7];
    const float* Wf1 = (const float*)d_in[8];
    const float* bf1 = (const float*)d_in[9];
    const float* Wf2 = (const float*)d_in[10];
    const float* bf2 = (const float*)d_in[11];
    const float* Wf3 = (const float*)d_in[12];
    const float* bf3 = (const float*)d_in[13];
    float* out = (float*)d_out;

    const int B = in_sizes[0] / (NN * 12);
    const int E = in_sizes[1] / 2;

    prep_kernel<<<1, 256>>>(ei, E);

    static int smem_set = 0;
    if (!smem_set) {
        cudaFuncSetAttribute(gcn_fused_kernel,
                             cudaFuncAttributeMaxDynamicSharedMemorySize,
                             SM_BYTES);
        smem_set = 1;
    }

    const int blocks = (B + BT - 1) / BT;
    gcn_fused_kernel<<<blocks, THREADS, SM_BYTES>>>(
        x, W1, b1, W2, b2, W3, b3, Wf1, bf1, Wf2, bf2, Wf3, bf3,
        out, B);
}